// round 15
// baseline (speedup 1.0000x reference)
#include <cuda_runtime.h>
#include <cuda_bf16.h>
#include <cstdint>
#include <math.h>

#define BATCH 128
typedef unsigned long long ull;

// ---------------- f32x2 packed helpers (conv1 direct kernel) ---------------
__device__ __forceinline__ void fma2(ull& d, ull a, ull b) {
    asm("fma.rn.f32x2 %0, %1, %2, %0;" : "+l"(d) : "l"(a), "l"(b));
}
__device__ __forceinline__ ull bcast2(float x) {
    ull r; asm("mov.b64 %0, {%1, %1};" : "=l"(r) : "f"(x)); return r;
}
__device__ __forceinline__ ull pack2(float lo, float hi) {
    ull r; asm("mov.b64 %0, {%1, %2};" : "=l"(r) : "f"(lo), "f"(hi)); return r;
}
union F4U { float4 v; ull u[2]; };
union UF2 { ull u; float f[2]; };

// ---------------- HMMA helpers ----------------------------------------------
__device__ __forceinline__ uint32_t smem_u32(const void* p) {
    uint32_t a;
    asm("{ .reg .u64 t; cvta.to.shared.u64 t, %1; cvt.u32.u64 %0, t; }" : "=r"(a) : "l"(p));
    return a;
}
#define LDMX4(R, ADDR) \
    asm volatile("ldmatrix.sync.aligned.m8n8.x4.shared.b16 {%0,%1,%2,%3}, [%4];" \
        : "=r"((R)[0]), "=r"((R)[1]), "=r"((R)[2]), "=r"((R)[3]) : "r"(ADDR))

__device__ __forceinline__ void mma_bf16(float* d, const uint32_t* a, const uint32_t* b) {
    asm volatile(
        "mma.sync.aligned.m16n8k16.row.col.f32.bf16.bf16.f32 "
        "{%0,%1,%2,%3}, {%4,%5,%6,%7}, {%8,%9}, {%0,%1,%2,%3};"
        : "+f"(d[0]), "+f"(d[1]), "+f"(d[2]), "+f"(d[3])
        : "r"(a[0]), "r"(a[1]), "r"(a[2]), "r"(a[3]), "r"(b[0]), "r"(b[1]));
}

__device__ __forceinline__ uint32_t packbf2(float x, float y) {
    __nv_bfloat162 t = __floats2bfloat162_rn(x, y);
    return *(uint32_t*)&t;
}

// packed split: u32 = (hi bf16) | (lo bf16 << 16), where v ~= hi + lo
__device__ __forceinline__ uint32_t packsplit(float v) {
    __nv_bfloat16 h = __float2bfloat16(v);
    float lo = v - __bfloat162float(h);
    __nv_bfloat16 l = __float2bfloat16(lo);
    unsigned short hu = *(unsigned short*)&h, lu = *(unsigned short*)&l;
    return (uint32_t)hu | ((uint32_t)lu << 16);
}

// fast tanh via hardware EX2: tanh(x) = 1 - 2/(e^{2x}+1)
__device__ __forceinline__ float fast_tanh(float x) {
    float e = __expf(2.f * x);
    return 1.f - __fdividef(2.f, e + 1.f);
}

// ---------------- scratch --------------------------------------------------
__device__ float g_A[33554432];
__device__ float g_B[8388608];
__device__ float g_X[16 * 128 * 592];
__device__ float g_H[16 * 128 * 600];
__device__ float g_P1[16 * 128 * 10];
__device__ float g_mean[128];
__device__ float g_var[128];
__device__ double g_stat[512];
__device__ __nv_bfloat16 g_wh[6856704];
__device__ __nv_bfloat16 g_wl[6856704];

__device__ const int c_nidx[16][8] = {
    {1, 4, 5, -1, -1, -1, -1, -1},
    {0, 2, 5, 4, 6, -1, -1, -1},
    {1, 3, 6, 5, 7, -1, -1, -1},
    {2, 7, 6, -1, -1, -1, -1, -1},
    {0, 5, 8, 1, 9, -1, -1, -1},
    {1, 4, 6, 9, 0, 2, 8, 10},
    {2, 5, 7, 10, 1, 3, 9, 11},
    {3, 6, 11, 2, 10, -1, -1, -1},
    {4, 9, 12, 5, 13, -1, -1, -1},
    {5, 8, 10, 13, 4, 6, 12, 14},
    {6, 9, 11, 14, 5, 7, 13, 15},
    {7, 10, 15, 6, 14, -1, -1, -1},
    {8, 13, 9, -1, -1, -1, -1, -1},
    {9, 12, 14, 8, 10, -1, -1, -1},
    {10, 13, 15, 9, 11, -1, -1, -1},
    {11, 14, 10, -1, -1, -1, -1, -1},
};

// ---------------- one-shot split of ALL conv weights + stat zeroing ---------
__global__ void split_all(const float* __restrict__ w2, const float* __restrict__ w3,
                          const float* __restrict__ w4, const float* __restrict__ w5,
                          const float* __restrict__ w6, const float* __restrict__ w7,
                          __nv_bfloat16* __restrict__ wh, __nv_bfloat16* __restrict__ wl,
                          double* __restrict__ stat)
{
    int i = blockIdx.x * 256 + threadIdx.x;
    if (i < 512) stat[i] = 0.0;
    if (i >= 6856704) return;
    const float* src; int off;
    if      (i <   73728) { src = w2; off = 0; }
    else if (i <  368640) { src = w3; off = 73728; }
    else if (i <  958464) { src = w4; off = 368640; }
    else if (i < 2138112) { src = w5; off = 958464; }
    else if (i < 4497408) { src = w6; off = 2138112; }
    else                  { src = w7; off = 4497408; }
    float v = src[i - off];
    __nv_bfloat16 h = __float2bfloat16(v);
    wh[i] = h;
    wl[i] = __float2bfloat16(v - __bfloat162float(h));
}

// ============================================================================
// HMMA bf16x3 implicit-GEMM conv with pre-split inputs (unchanged winner).
// ============================================================================
static constexpr int HB_DSM = 65536 + 1024;

template<int Cin, int Cout, int H, int W, bool RELU, bool PACKOUT, int KSPLIT = 1>
__global__ __launch_bounds__(256, 2)
void conv_hmma(const uint32_t* __restrict__ in,
               const __nv_bfloat16* __restrict__ wh, const __nv_bfloat16* __restrict__ wl,
               const float* __restrict__ bias, float* __restrict__ out)
{
    constexpr int K  = Cin * 9;
    constexpr int HW = H * W;
    constexpr int NC  = K / 32;
    constexpr int NCZ = NC / KSPLIT;

    extern __shared__ char dsm_raw[];
    const uint32_t sb = (smem_u32(dsm_raw) + 1023u) & ~1023u;

    const int tid  = threadIdx.x;
    const int wid  = tid >> 5;
    const int lane = tid & 31;
    const int wm   = wid & 1;
    const int wn   = wid >> 1;
    const int n0   = blockIdx.x * 128;
    const int m0   = blockIdx.y * 128;
    const int kc0  = (KSPLIT > 1) ? blockIdx.z * NCZ : 0;
    if (KSPLIT > 1) out += (size_t)blockIdx.z * Cout * (BATCH * HW);

    const int lr = tid >> 1;
    const int lh = tid & 1;
    const int gn = n0 + lr;
    const int bidx = gn / HW;
    const int p    = gn & (HW - 1);
    const int y0   = p / W;
    const int x0   = p & (W - 1);
    const uint32_t* srcb = in + bidx * Cin * HW;
    const __nv_bfloat16* whp0 = wh + (m0 + lr) * K + lh * 16;
    const __nv_bfloat16* wlp0 = wl + (m0 + lr) * K + lh * 16;

    float acc[4][4][4];
    #pragma unroll
    for (int mt = 0; mt < 4; mt++)
        #pragma unroll
        for (int nt = 0; nt < 4; nt++)
            #pragma unroll
            for (int e = 0; e < 4; e++) acc[mt][nt][e] = 0.f;

    auto swz = [](int row, int ch) { return row * 64 + ((ch ^ ((row >> 1) & 3)) << 4); };
    const int c0 = 2 * lh;

    auto load_tiles = [&](int s, int kc) {
        const uint32_t tb = sb + s * 32768;
        {
            const uint4* ph = (const uint4*)(whp0 + kc * 32);
            const uint4* pl = (const uint4*)(wlp0 + kc * 32);
            uint4 h0 = __ldg(ph), h1 = __ldg(ph + 1);
            uint4 l0 = __ldg(pl), l1 = __ldg(pl + 1);
            asm volatile("st.shared.v4.b32 [%0], {%1,%2,%3,%4};" ::
                "r"(tb + swz(lr, c0)), "r"(h0.x), "r"(h0.y), "r"(h0.z), "r"(h0.w));
            asm volatile("st.shared.v4.b32 [%0], {%1,%2,%3,%4};" ::
                "r"(tb + swz(lr, c0 + 1)), "r"(h1.x), "r"(h1.y), "r"(h1.z), "r"(h1.w));
            asm volatile("st.shared.v4.b32 [%0], {%1,%2,%3,%4};" ::
                "r"(tb + 8192 + swz(lr, c0)), "r"(l0.x), "r"(l0.y), "r"(l0.z), "r"(l0.w));
            asm volatile("st.shared.v4.b32 [%0], {%1,%2,%3,%4};" ::
                "r"(tb + 8192 + swz(lr, c0 + 1)), "r"(l1.x), "r"(l1.y), "r"(l1.z), "r"(l1.w));
        }
        {
            int k = kc * 32 + lh * 16;
            int ci = k / 9;
            int f  = k - 9 * ci;
            int cioff = ci * HW;
            uint32_t w[16];
            #pragma unroll
            for (int j = 0; j < 16; j++) {
                int dy = (f * 11) >> 5;
                int dx = f - 3 * dy;
                int y = y0 + dy - 1, x = x0 + dx - 1;
                w[j] = ((unsigned)y < (unsigned)H && (unsigned)x < (unsigned)W)
                         ? __ldg(srcb + cioff + y * W + x) : 0u;
                f++; if (f == 9) { f = 0; cioff += HW; }
            }
            uint32_t Hw[8], Lw[8];
            #pragma unroll
            for (int j = 0; j < 8; j++) {
                Hw[j] = __byte_perm(w[2 * j], w[2 * j + 1], 0x5410);
                Lw[j] = __byte_perm(w[2 * j], w[2 * j + 1], 0x7632);
            }
            const uint32_t bb = tb + 16384;
            asm volatile("st.shared.v4.b32 [%0], {%1,%2,%3,%4};" ::
                "r"(bb + swz(lr, c0)), "r"(Hw[0]), "r"(Hw[1]), "r"(Hw[2]), "r"(Hw[3]));
            asm volatile("st.shared.v4.b32 [%0], {%1,%2,%3,%4};" ::
                "r"(bb + swz(lr, c0 + 1)), "r"(Hw[4]), "r"(Hw[5]), "r"(Hw[6]), "r"(Hw[7]));
            asm volatile("st.shared.v4.b32 [%0], {%1,%2,%3,%4};" ::
                "r"(bb + 8192 + swz(lr, c0)), "r"(Lw[0]), "r"(Lw[1]), "r"(Lw[2]), "r"(Lw[3]));
            asm volatile("st.shared.v4.b32 [%0], {%1,%2,%3,%4};" ::
                "r"(bb + 8192 + swz(lr, c0 + 1)), "r"(Lw[4]), "r"(Lw[5]), "r"(Lw[6]), "r"(Lw[7]));
        }
    };

    load_tiles(0, kc0);
    __syncthreads();

    for (int j = 0; j < NCZ; j++) {
        const int s = j & 1;
        if (j + 1 < NCZ) load_tiles(s ^ 1, kc0 + j + 1);

        const uint32_t aB = sb + s * 32768;
        const uint32_t bB = aB + 16384;

        #pragma unroll
        for (int ks = 0; ks < 2; ks++) {
            uint32_t bh[4][2], bl[4][2];
            #pragma unroll
            for (int ntp = 0; ntp < 2; ntp++) {
                int row = wn * 32 + ntp * 16 + ((lane >> 4) & 1) * 8 + (lane & 7);
                int ch  = ks * 2 + ((lane >> 3) & 1);
                uint32_t off = swz(row, ch);
                uint32_t t4[4];
                LDMX4(t4, bB + off);
                bh[ntp*2][0] = t4[0]; bh[ntp*2][1] = t4[1];
                bh[ntp*2+1][0] = t4[2]; bh[ntp*2+1][1] = t4[3];
                LDMX4(t4, bB + 8192 + off);
                bl[ntp*2][0] = t4[0]; bl[ntp*2][1] = t4[1];
                bl[ntp*2+1][0] = t4[2]; bl[ntp*2+1][1] = t4[3];
            }
            const int arow = wm * 64 + (lane & 7) + ((lane >> 3) & 1) * 8;
            const int ach  = ks * 2 + (lane >> 4);
            #pragma unroll
            for (int mt = 0; mt < 4; mt++) {
                uint32_t ah[4], al[4];
                int row = arow + mt * 16;
                uint32_t off = swz(row, ach);
                LDMX4(ah, aB + off);
                LDMX4(al, aB + 8192 + off);
                #pragma unroll
                for (int nt = 0; nt < 4; nt++) {
                    mma_bf16(acc[mt][nt], ah, bh[nt]);
                    mma_bf16(acc[mt][nt], ah, bl[nt]);
                    mma_bf16(acc[mt][nt], al, bh[nt]);
                }
            }
        }
        __syncthreads();
    }

    #pragma unroll
    for (int mt = 0; mt < 4; mt++) {
        #pragma unroll
        for (int nt = 0; nt < 4; nt++) {
            int r0 = m0 + wm * 64 + mt * 16 + (lane >> 2);
            int cc = n0 + wn * 32 + nt * 8 + ((lane & 3) << 1);
            int b  = cc / HW;
            int pp = cc & (HW - 1);
            #pragma unroll
            for (int hh = 0; hh < 2; hh++) {
                int row = r0 + hh * 8;
                float bv = (KSPLIT == 1 || blockIdx.z == 0) ? bias[row] : 0.f;
                float2 v;
                v.x = acc[mt][nt][hh * 2 + 0] + bv;
                v.y = acc[mt][nt][hh * 2 + 1] + bv;
                if (RELU) { v.x = fmaxf(v.x, 0.f); v.y = fmaxf(v.y, 0.f); }
                if (PACKOUT) {
                    uint2 o;
                    o.x = packsplit(v.x);
                    o.y = packsplit(v.y);
                    *(uint2*)&((uint32_t*)out)[(b * Cout + row) * HW + pp] = o;
                } else {
                    *(float2*)&out[(b * Cout + row) * HW + pp] = v;
                }
            }
        }
    }
}

// ============================================================================
// HMMA bf16x3 head GEMM: G[node][m][n] = F[node][m][:512] . W1[node][80+k][n] + b1
// BM=128 (batch), BN=128 (5 blocks cover N=600), BK=32, K=512. Inline split.
// ============================================================================
__global__ __launch_bounds__(256, 2)
void hmma_feats(const float* __restrict__ F, const float* __restrict__ W1,
                const float* __restrict__ b1, float* __restrict__ G)
{
    constexpr int K = 512, NC = 16, N = 600;
    extern __shared__ char dsm_raw[];
    const uint32_t sb = (smem_u32(dsm_raw) + 1023u) & ~1023u;

    const int tid  = threadIdx.x;
    const int wid  = tid >> 5;
    const int lane = tid & 31;
    const int wm   = wid & 1;
    const int wn   = wid >> 1;
    const int n0   = blockIdx.x * 128;
    const int node = blockIdx.y;

    const int lr = tid >> 1;
    const int lh = tid & 1;
    const float* Fb = F + node * 128 * K + lr * K + lh * 16;
    const float* Wb = W1 + node * 592 * N + 80 * N;   // rows 80..591
    const float* bb1 = b1 + node * N;
    const int gn = n0 + lr;                            // this thread's B row (n)
    const bool nok = (gn < N);

    float acc[4][4][4];
    #pragma unroll
    for (int mt = 0; mt < 4; mt++)
        #pragma unroll
        for (int nt = 0; nt < 4; nt++)
            #pragma unroll
            for (int e = 0; e < 4; e++) acc[mt][nt][e] = 0.f;

    auto swz = [](int row, int ch) { return row * 64 + ((ch ^ ((row >> 1) & 3)) << 4); };
    const int c0 = 2 * lh;

    auto load_tiles = [&](int s, int kc) {
        const uint32_t tb = sb + s * 32768;
        // A: F rows, 16 contiguous floats, split inline
        {
            const float* fp = Fb + kc * 32;
            float4 w0 = *(const float4*)(fp + 0);
            float4 w1 = *(const float4*)(fp + 4);
            float4 w2 = *(const float4*)(fp + 8);
            float4 w3 = *(const float4*)(fp + 12);
            float v[16] = {w0.x,w0.y,w0.z,w0.w, w1.x,w1.y,w1.z,w1.w,
                           w2.x,w2.y,w2.z,w2.w, w3.x,w3.y,w3.z,w3.w};
            float hi[16], lo[16];
            #pragma unroll
            for (int j = 0; j < 16; j++) {
                __nv_bfloat16 h = __float2bfloat16(v[j]);
                hi[j] = __bfloat162float(h);
                lo[j] = v[j] - hi[j];
            }
            uint4 H0 = { packbf2(hi[0],hi[1]), packbf2(hi[2],hi[3]),
                         packbf2(hi[4],hi[5]), packbf2(hi[6],hi[7]) };
            uint4 H1 = { packbf2(hi[8],hi[9]), packbf2(hi[10],hi[11]),
                         packbf2(hi[12],hi[13]), packbf2(hi[14],hi[15]) };
            uint4 L0 = { packbf2(lo[0],lo[1]), packbf2(lo[2],lo[3]),
                         packbf2(lo[4],lo[5]), packbf2(lo[6],lo[7]) };
            uint4 L1 = { packbf2(lo[8],lo[9]), packbf2(lo[10],lo[11]),
                         packbf2(lo[12],lo[13]), packbf2(lo[14],lo[15]) };
            asm volatile("st.shared.v4.b32 [%0], {%1,%2,%3,%4};" ::
                "r"(tb + swz(lr, c0)), "r"(H0.x), "r"(H0.y), "r"(H0.z), "r"(H0.w));
            asm volatile("st.shared.v4.b32 [%0], {%1,%2,%3,%4};" ::
                "r"(tb + swz(lr, c0 + 1)), "r"(H1.x), "r"(H1.y), "r"(H1.z), "r"(H1.w));
            asm volatile("st.shared.v4.b32 [%0], {%1,%2,%3,%4};" ::
                "r"(tb + 8192 + swz(lr, c0)), "r"(L0.x), "r"(L0.y), "r"(L0.z), "r"(L0.w));
            asm volatile("st.shared.v4.b32 [%0], {%1,%2,%3,%4};" ::
                "r"(tb + 8192 + swz(lr, c0 + 1)), "r"(L1.x), "r"(L1.y), "r"(L1.z), "r"(L1.w));
        }
        // B: W1 column gather (stride N), split inline
        {
            int k = kc * 32 + lh * 16;
            float v[16];
            #pragma unroll
            for (int j = 0; j < 16; j++)
                v[j] = nok ? __ldg(Wb + (k + j) * N + gn) : 0.f;
            float hi[16], lo[16];
            #pragma unroll
            for (int j = 0; j < 16; j++) {
                __nv_bfloat16 h = __float2bfloat16(v[j]);
                hi[j] = __bfloat162float(h);
                lo[j] = v[j] - hi[j];
            }
            uint4 H0 = { packbf2(hi[0],hi[1]), packbf2(hi[2],hi[3]),
                         packbf2(hi[4],hi[5]), packbf2(hi[6],hi[7]) };
            uint4 H1 = { packbf2(hi[8],hi[9]), packbf2(hi[10],hi[11]),
                         packbf2(hi[12],hi[13]), packbf2(hi[14],hi[15]) };
            uint4 L0 = { packbf2(lo[0],lo[1]), packbf2(lo[2],lo[3]),
                         packbf2(lo[4],lo[5]), packbf2(lo[6],lo[7]) };
            uint4 L1 = { packbf2(lo[8],lo[9]), packbf2(lo[10],lo[11]),
                         packbf2(lo[12],lo[13]), packbf2(lo[14],lo[15]) };
            const uint32_t bbuf = tb + 16384;
            asm volatile("st.shared.v4.b32 [%0], {%1,%2,%3,%4};" ::
                "r"(bbuf + swz(lr, c0)), "r"(H0.x), "r"(H0.y), "r"(H0.z), "r"(H0.w));
            asm volatile("st.shared.v4.b32 [%0], {%1,%2,%3,%4};" ::
                "r"(bbuf + swz(lr, c0 + 1)), "r"(H1.x), "r"(H1.y), "r"(H1.z), "r"(H1.w));
            asm volatile("st.shared.v4.b32 [%0], {%1,%2,%3,%4};" ::
                "r"(bbuf + 8192 + swz(lr, c0)), "r"(L0.x), "r"(L0.y), "r"(L0.z), "r"(L0.w));
            asm volatile("st.shared.v4.b32 [%0], {%1,%2,%3,%4};" ::
                "r"(bbuf + 8192 + swz(lr, c0 + 1)), "r"(L1.x), "r"(L1.y), "r"(L1.z), "r"(L1.w));
        }
    };

    load_tiles(0, 0);
    __syncthreads();

    for (int j = 0; j < NC; j++) {
        const int s = j & 1;
        if (j + 1 < NC) load_tiles(s ^ 1, j + 1);

        const uint32_t aB = sb + s * 32768;
        const uint32_t bB = aB + 16384;

        #pragma unroll
        for (int ks = 0; ks < 2; ks++) {
            uint32_t bh[4][2], bl[4][2];
            #pragma unroll
            for (int ntp = 0; ntp < 2; ntp++) {
                int row = wn * 32 + ntp * 16 + ((lane >> 4) & 1) * 8 + (lane & 7);
                int ch  = ks * 2 + ((lane >> 3) & 1);
                uint32_t off = swz(row, ch);
                uint32_t t4[4];
                LDMX4(t4, bB + off);
                bh[ntp*2][0] = t4[0]; bh[ntp*2][1] = t4[1];
                bh[ntp*2+1][0] = t4[2]; bh[ntp*2+1][1] = t4[3];
                LDMX4(t4, bB + 8192 + off);
                bl[ntp*2][0] = t4[0]; bl[ntp*2][1] = t4[1];
                bl[ntp*2+1][0] = t4[2]; bl[ntp*2+1][1] = t4[3];
            }
            const int arow = wm * 64 + (lane & 7) + ((lane >> 3) & 1) * 8;
            const int ach  = ks * 2 + (lane >> 4);
            #pragma unroll
            for (int mt = 0; mt < 4; mt++) {
                uint32_t ah[4], al[4];
                int row = arow + mt * 16;
                uint32_t off = swz(row, ach);
                LDMX4(ah, aB + off);
                LDMX4(al, aB + 8192 + off);
                #pragma unroll
                for (int nt = 0; nt < 4; nt++) {
                    mma_bf16(acc[mt][nt], ah, bh[nt]);
                    mma_bf16(acc[mt][nt], ah, bl[nt]);
                    mma_bf16(acc[mt][nt], al, bh[nt]);
                }
            }
        }
        __syncthreads();
    }

    // epilogue: bias per COLUMN, guard n < 600
    float* Gb = G + node * 128 * N;
    #pragma unroll
    for (int mt = 0; mt < 4; mt++) {
        #pragma unroll
        for (int nt = 0; nt < 4; nt++) {
            int r0 = wm * 64 + mt * 16 + (lane >> 2);
            int cc = n0 + wn * 32 + nt * 8 + ((lane & 3) << 1);
            if (cc >= N) continue;
            float2 bv = *(const float2*)&bb1[cc];
            #pragma unroll
            for (int hh = 0; hh < 2; hh++) {
                int row = r0 + hh * 8;
                float2 v;
                v.x = acc[mt][nt][hh * 2 + 0] + bv.x;
                v.y = acc[mt][nt][hh * 2 + 1] + bv.y;
                *(float2*)&Gb[row * N + cc] = v;
            }
        }
    }
}

// ============================================================================
// conv1 (3->64) direct conv + FUSED BN-stat accumulation (unchanged winner).
// ============================================================================
__global__ __launch_bounds__(256) void conv1_direct_stats(
    const float* __restrict__ in, const float* __restrict__ wgt,
    const float* __restrict__ bias, float* __restrict__ out,
    double* __restrict__ stat)
{
    __shared__ __align__(16) float wT[27][64];
    __shared__ float inr[3][3][66];
    __shared__ float sval[64][65];

    const int tid = threadIdx.x;
    const int b   = blockIdx.x >> 6;
    const int y   = blockIdx.x & 63;
    const int x   = tid & 63;
    const int cog = tid >> 6;

    for (int i = tid; i < 1728; i += 256) {
        int co = i / 27, k = i - co * 27;
        wT[k][co] = wgt[i];
    }
    for (int i = tid; i < 594; i += 256) {
        int ci = i / 198, rem = i - ci * 198;
        int dy = rem / 66, xx = rem - dy * 66;
        int yy = y - 1 + dy, gx = xx - 1;
        float v = 0.f;
        if ((unsigned)yy < 64u && (unsigned)gx < 64u)
            v = in[(b * 3 + ci) * 4096 + yy * 64 + gx];
        inr[ci][dy][xx] = v;
    }
    __syncthreads();

    float iv[27];
    #pragma unroll
    for (int ci = 0; ci < 3; ci++)
        #pragma unroll
        for (int dy = 0; dy < 3; dy++)
            #pragma unroll
            for (int dx = 0; dx < 3; dx++)
                iv[ci * 9 + dy * 3 + dx] = inr[ci][dy][x + dx];

    ull acc2[8];
    #pragma unroll
    for (int p = 0; p < 8; p++) {
        float2 bb = *(const float2*)&bias[cog * 16 + p * 2];
        acc2[p] = pack2(bb.x, bb.y);
    }
    #pragma unroll
    for (int k = 0; k < 27; k++) {
        ull v2 = bcast2(iv[k]);
        F4U w0, w1, w2, w3;
        w0.v = *(const float4*)&wT[k][cog * 16 + 0];
        w1.v = *(const float4*)&wT[k][cog * 16 + 4];
        w2.v = *(const float4*)&wT[k][cog * 16 + 8];
        w3.v = *(const float4*)&wT[k][cog * 16 + 12];
        fma2(acc2[0], w0.u[0], v2); fma2(acc2[1], w0.u[1], v2);
        fma2(acc2[2], w1.u[0], v2); fma2(acc2[3], w1.u[1], v2);
        fma2(acc2[4], w2.u[0], v2); fma2(acc2[5], w2.u[1], v2);
        fma2(acc2[6], w3.u[0], v2); fma2(acc2[7], w3.u[1], v2);
    }

    #pragma unroll
    for (int p = 0; p < 8; p++) {
        UF2 u; u.u = acc2[p];
        #pragma unroll
        for (int h = 0; h < 2; h++) {
            int co = cog * 16 + p * 2 + h;
            float val = u.f[h];
            out[(b * 64 + co) * 4096 + y * 64 + x] = val;
            sval[co][x] = val;
        }
    }
    __syncthreads();

    if (tid < 64) {
        float s = 0.f, q = 0.f;
        #pragma unroll 8
        for (int px = 0; px < 64; px++) {
            float v = sval[tid][px];
            s += v;
            q += v * v;
        }
        atomicAdd(&stat[tid],      (double)s);
        atomicAdd(&stat[64 + tid], (double)q);
    }
}

// ---------------- BN stats (conv2 only) --------------------------------------
__global__ void bn_stats_slab(const float* __restrict__ x, double* __restrict__ stat,
                              int C, int HW, int hwsh)
{
    int c  = blockIdx.x;
    int b0 = blockIdx.y * 8;
    __shared__ double ss[256], sq[256];
    double s = 0.0, q = 0.0;
    int elems = 8 * HW;
    for (int j = threadIdx.x; j < elems; j += 256) {
        int b = b0 + (j >> hwsh);
        int p = j & (HW - 1);
        float v = x[(b * C + c) * HW + p];
        s += (double)v;
        q += (double)v * (double)v;
    }
    ss[threadIdx.x] = s; sq[threadIdx.x] = q;
    __syncthreads();
    for (int st = 128; st > 0; st >>= 1) {
        if (threadIdx.x < st) {
            ss[threadIdx.x] += ss[threadIdx.x + st];
            sq[threadIdx.x] += sq[threadIdx.x + st];
        }
        __syncthreads();
    }
    if (threadIdx.x == 0) {
        atomicAdd(&stat[c],     ss[0]);
        atomicAdd(&stat[C + c], sq[0]);
    }
}

__global__ void finalize_stats(const double* __restrict__ stat,
                               float* __restrict__ mean, float* __restrict__ var,
                               int C, double inv)
{
    int c = threadIdx.x;
    if (c < C) {
        double m = stat[c] * inv;
        mean[c] = (float)m;
        var[c]  = (float)(stat[C + c] * inv - m * m);
    }
}

// ---------------- fused BN + ReLU + MaxPool(3,2,1), packed-split output -----
__global__ void bn_relu_pool2(const float* __restrict__ in, uint32_t* __restrict__ out,
                              const float* __restrict__ g, const float* __restrict__ bta,
                              const float* __restrict__ mean, const float* __restrict__ var,
                              int totalp, int H, int owsh, int cmask)
{
    int OW = H >> 1;
    for (int i = blockIdx.x * blockDim.x + threadIdx.x; i < totalp;
         i += gridDim.x * blockDim.x) {
        int oxp = i & ((1 << (owsh - 1)) - 1);
        int t   = i >> (owsh - 1);
        int oy  = t & (OW - 1);
        int bc  = t >> owsh;
        int c   = bc & cmask;
        float scale = g[c] * rsqrtf(var[c] + 1e-5f);
        float shift = bta[c] - mean[c] * scale;
        const float* src = in + (long long)bc * H * H;
        int xb = 4 * oxp - 1;
        float m0 = 0.f, m1 = 0.f;
        #pragma unroll
        for (int dy = 0; dy < 3; dy++) {
            int y = 2 * oy - 1 + dy;
            if ((unsigned)y >= (unsigned)H) continue;
            const float* row = src + y * H;
            float v[5];
            #pragma unroll
            for (int j = 0; j < 5; j++) {
                int x = xb + j;
                v[j] = ((unsigned)x < (unsigned)H) ? fmaf(row[x], scale, shift) : 0.f;
            }
            m0 = fmaxf(m0, fmaxf(fmaxf(v[0], v[1]), v[2]));
            m1 = fmaxf(m1, fmaxf(fmaxf(v[2], v[3]), v[4]));
        }
        uint2 o;
        o.x = packsplit(m0);
        o.y = packsplit(m1);
        *(uint2*)&out[(bc * OW + oy) * OW + 2 * oxp] = o;
    }
}

// ---------------- MaxPool2d(3,2,1), packed-split output ---------------------
__global__ void maxpool3s2(const float* __restrict__ in, uint32_t* __restrict__ out,
                           int total, int H, int W, int owsh)
{
    int OW = W >> 1;
    for (int i = blockIdx.x * blockDim.x + threadIdx.x; i < total;
         i += gridDim.x * blockDim.x) {
        int ox = i & (OW - 1);
        int t  = i >> owsh;
        int oy = t & (OW - 1);
        int bc = t >> owsh;
        const float* src = in + (long long)bc * H * W;
        float m = -INFINITY;
        #pragma unroll
        for (int dy = 0; dy < 3; dy++) {
            int y = 2 * oy - 1 + dy;
            if ((unsigned)y >= (unsigned)H) continue;
            #pragma unroll
            for (int dx = 0; dx < 3; dx++) {
                int x = 2 * ox - 1 + dx;
                if ((unsigned)x >= (unsigned)W) continue;
                m = fmaxf(m, src[y * W + x]);
            }
        }
        out[i] = packsplit(m);
    }
}

// ---------------- head: G += neigh @ W1[0:80] (K=80, scalar) ----------------
__global__ __launch_bounds__(256) void gemm_neigh_add(
    const float* __restrict__ A, const float* __restrict__ Bw,
    float* __restrict__ C)
{
    const int M = 128, N = 600, KA = 80;
    const int node = blockIdx.z;
    A  += node * M * KA;
    Bw += node * 592 * N;
    C  += node * M * N;

    __shared__ __align__(16) float As[16][68];
    __shared__ __align__(16) float Bs[16][68];

    const int tid = threadIdx.x;
    const int m0 = blockIdx.y * 64;
    const int n0 = blockIdx.x * 64;
    const int tm = tid >> 4;
    const int tn = tid & 15;

    float acc[4][4] = {};

    for (int k0 = 0; k0 < KA; k0 += 16) {
        #pragma unroll
        for (int i = 0; i < 4; i++) {
            int lin = tid + i * 256;
            int kk = lin & 15;
            int mm = lin >> 4;
            As[kk][mm] = A[(m0 + mm) * KA + k0 + kk];
        }
        #pragma unroll
        for (int i = 0; i < 4; i++) {
            int lin = tid + i * 256;
            int nn = lin & 63;
            int kk = lin >> 6;
            int gn = n0 + nn;
            Bs[kk][nn] = (gn < N) ? Bw[(k0 + kk) * N + gn] : 0.f;
        }
        __syncthreads();
        #pragma unroll
        for (int kk = 0; kk < 16; kk++) {
            float4 a4 = *(const float4*)&As[kk][tm * 4];
            float4 b4 = *(const float4*)&Bs[kk][tn * 4];
            float av[4] = {a4.x, a4.y, a4.z, a4.w};
            float bv[4] = {b4.x, b4.y, b4.z, b4.w};
            #pragma unroll
            for (int i = 0; i < 4; i++)
                #pragma unroll
                for (int j = 0; j < 4; j++)
                    acc[i][j] = fmaf(av[i], bv[j], acc[i][j]);
        }
        __syncthreads();
    }

    #pragma unroll
    for (int i = 0; i < 4; i++) {
        int m = m0 + tm * 4 + i;
        #pragma unroll
        for (int j = 0; j < 4; j++) {
            int gn = n0 + tn * 4 + j;
            if (gn < N)
                C[m * N + gn] += acc[i][j];
        }
    }
}

// ---------------- MLP stage 2 + softmax (fast tanh fused on load) -----------
__global__ void mlp2_softmax_tanh(const float* __restrict__ h, const float* __restrict__ W2,
                                  const float* __restrict__ b2, float* __restrict__ out)
{
    int nb = blockIdx.x;
    int node = nb >> 7;
    int b    = nb & 127;
    int lane = threadIdx.x;

    const float* hrow = h  + (node * 128 + b) * 600;
    const float* w    = W2 + node * 600 * 10;

    float acc[10];
    #pragma unroll
    for (int o = 0; o < 10; o++) acc[o] = 0.f;

    for (int i = lane; i < 600; i += 32) {
        float hv = fast_tanh(hrow[i]);
        const float* wr = w + i * 10;
        #pragma unroll
        for (int o = 0; o < 10; o++)
            acc[o] = fmaf(hv, wr[o], acc[o]);
    }
    #pragma unroll
    for (int o = 0; o < 10; o++)
        #pragma unroll
        for (int s = 16; s > 0; s >>= 1)
            acc[o] += __shfl_down_sync(0xffffffffu, acc[o], s);

    if (lane == 0) {
        float lg[10];
        float mx = -INFINITY;
        #pragma unroll
        for (int o = 0; o < 10; o++) {
            lg[o] = acc[o] + b2[node * 10 + o];
            mx = fmaxf(mx, lg[o]);
        }
        float se = 0.f;
        #pragma unroll
        for (int o = 0; o < 10; o++) { lg[o] = __expf(lg[o] - mx); se += lg[o]; }
        float inv = __fdividef(1.f, se);
        #pragma unroll
        for (int o = 0; o < 10; o++)
            out[(node * 128 + b) * 10 + o] = lg[o] * inv;
    }
}

// ---------------- head glue ---------------------------------------------------
__global__ void build_F(const float* __restrict__ p, float* __restrict__ F, int total)
{
    for (int i = blockIdx.x * blockDim.x + threadIdx.x; i < total;
         i += gridDim.x * blockDim.x) {
        int cf = i & 511;
        int t  = i >> 9;
        int b  = t & 127;
        int n  = t >> 7;
        int idx = ((b * 512 + cf) << 4) + n;
        float v = p[idx] + p[idx + 1048576] + p[idx + 2097152] + p[idx + 3145728];
        F[i] = fmaxf(v, 0.f);
    }
}

__global__ void build_neigh(const float* __restrict__ P1, float* __restrict__ NG, int total)
{
    for (int i = blockIdx.x * blockDim.x + threadIdx.x; i < total;
         i += gridDim.x * blockDim.x) {
        int j = i % 80;
        int t = i / 80;
        int b = t & 127;
        int n = t >> 7;
        int s   = j / 10;
        int cls = j - s * 10;
        int nb  = c_nidx[n][s];
        float v = (nb >= 0) ? P1[(nb * 128 + b) * 10 + cls] : 0.f;
        NG[(n * 128 + b) * 80 + j] = v;
    }
}

__global__ void final_mean_sq(const float* __restrict__ preds2, float* __restrict__ out)
{
    int t = blockIdx.x * blockDim.x + threadIdx.x;
    if (t >= 1280) return;
    int b = t / 10, c = t - (t / 10) * 10;
    float s = 0.f;
    #pragma unroll
    for (int n = 0; n < 16; n++)
        s += preds2[(n * 128 + b) * 10 + c];
    s *= (1.f / 16.f);
    out[t] = s * s;
}

// ---------------- launcher -----------------------------------------------------
extern "C" void kernel_launch(void* const* d_in, const int* in_sizes, int n_in,
                              void* d_out, int out_size)
{
    const float* x     = (const float*)d_in[0];
    const float* cw1   = (const float*)d_in[1];
    const float* cb1   = (const float*)d_in[2];
    const float* bn1g  = (const float*)d_in[3];
    const float* bn1b  = (const float*)d_in[4];
    const float* cw2   = (const float*)d_in[5];
    const float* cb2   = (const float*)d_in[6];
    const float* bn2g  = (const float*)d_in[7];
    const float* bn2b  = (const float*)d_in[8];
    const float* cw3   = (const float*)d_in[9];
    const float* cb3   = (const float*)d_in[10];
    const float* cw4   = (const float*)d_in[11];
    const float* cb4   = (const float*)d_in[12];
    const float* cw5   = (const float*)d_in[13];
    const float* cb5   = (const float*)d_in[14];
    const float* cw6   = (const float*)d_in[15];
    const float* cb6   = (const float*)d_in[16];
    const float* cw7   = (const float*)d_in[17];
    const float* cb7   = (const float*)d_in[18];
    const float* W1    = (const float*)d_in[19];
    const float* b1    = (const float*)d_in[20];
    const float* W2    = (const float*)d_in[21];
    const float* b2    = (const float*)d_in[22];
    float* out = (float*)d_out;

    float *A, *Bb, *X, *G, *P1, *mean, *var;
    double* stat;
    __nv_bfloat16 *wh, *wl;
    cudaGetSymbolAddress((void**)&A,    g_A);
    cudaGetSymbolAddress((void**)&Bb,   g_B);
    cudaGetSymbolAddress((void**)&X,    g_X);
    cudaGetSymbolAddress((void**)&G,    g_H);
    cudaGetSymbolAddress((void**)&P1,   g_P1);
    cudaGetSymbolAddress((void**)&mean, g_mean);
    cudaGetSymbolAddress((void**)&var,  g_var);
    cudaGetSymbolAddress((void**)&stat, g_stat);
    cudaGetSymbolAddress((void**)&wh,   g_wh);
    cudaGetSymbolAddress((void**)&wl,   g_wl);

    float* F  = X;
    float* NG = X + 1048576;

    const int o2 = 0, o3 = 73728, o4 = 368640, o5 = 958464, o6 = 2138112, o7 = 4497408;

    cudaFuncSetAttribute(conv_hmma<64, 128, 32, 32, false, false>,   cudaFuncAttributeMaxDynamicSharedMemorySize, HB_DSM);
    cudaFuncSetAttribute(conv_hmma<128, 256, 16, 16, true, true>,    cudaFuncAttributeMaxDynamicSharedMemorySize, HB_DSM);
    cudaFuncSetAttribute(conv_hmma<256, 256, 16, 16, true, false>,   cudaFuncAttributeMaxDynamicSharedMemorySize, HB_DSM);
    cudaFuncSetAttribute(conv_hmma<256, 512, 8, 8, true, true>,      cudaFuncAttributeMaxDynamicSharedMemorySize, HB_DSM);
    cudaFuncSetAttribute(conv_hmma<512, 512, 8, 8, true, false>,     cudaFuncAttributeMaxDynamicSharedMemorySize, HB_DSM);
    cudaFuncSetAttribute(conv_hmma<512, 512, 4, 4, false, false, 4>, cudaFuncAttributeMaxDynamicSharedMemorySize, HB_DSM);
    cudaFuncSetAttribute(hmma_feats, cudaFuncAttributeMaxDynamicSharedMemorySize, HB_DSM);

    // ---- split weights + zero stats (one launch; precedes conv1 in-stream)
    split_all<<<26785, 256>>>(cw2, cw3, cw4, cw5, cw6, cw7, wh, wl, stat);

    // ---- conv1 (3->64, 64x64) + fused BN1 stats + pool -> 32x32 (packed)
    conv1_direct_stats<<<8192, 256>>>(x, cw1, cb1, A, stat);
    finalize_stats<<<1, 128>>>(stat, mean, var, 64, 1.0 / 524288.0);
    bn_relu_pool2<<<16384, 256>>>(A, (uint32_t*)Bb, bn1g, bn1b, mean, var, 4194304, 64, 5, 63);

    // ---- conv2 (64->128, 32x32): packed in -> fp32 out (stats need it)
    conv_hmma<64, 128, 32, 32, false, false><<<dim3(1024, 1), 256, HB_DSM>>>(
        (const uint32_t*)Bb, wh + o2, wl + o2, cb2, A);
    bn_stats_slab<<<dim3(128, 16), 256>>>(A, stat + 128, 128, 1024, 10);
    finalize_stats<<<1, 128>>>(stat + 128, mean, var, 128, 1.0 / 131072.0);
    bn_relu_pool2<<<8192, 256>>>(A, (uint32_t*)Bb, bn2g, bn2b, mean, var, 2097152, 32, 4, 127);

    // ---- conv3 (packed -> packed), conv4 (packed -> fp32), pool -> packed
    conv_hmma<128, 256, 16, 16, true, true><<<dim3(256, 2), 256, HB_DSM>>>(
        (const uint32_t*)Bb, wh + o3, wl + o3, cb3, A);
    conv_hmma<256, 256, 16, 16, true, false><<<dim3(256, 2), 256, HB_DSM>>>(
        (const uint32_t*)A, wh + o4, wl + o4, cb4, Bb);
    maxpool3s2<<<4096, 256>>>(Bb, (uint32_t*)A, 2097152, 16, 16, 3);

    // ---- conv5 (packed -> packed), conv6 (packed -> fp32), pool -> packed
    conv_hmma<256, 512, 8, 8, true, true><<<dim3(64, 4), 256, HB_DSM>>>(
        (const uint32_t*)A, wh + o5, wl + o5, cb5, Bb);
    conv_hmma<512, 512, 8, 8, true, false><<<dim3(64, 4), 256, HB_DSM>>>(
        (const uint32_t*)Bb, wh + o6, wl + o6, cb6, A);
    maxpool3s2<<<2048, 256>>>(A, (uint32_t*)Bb, 1048576, 8, 8, 2);

    // ---- conv7 split-K=4 (packed in -> fp32 partials)
    conv_hmma<512, 512, 4, 4, false, false, 4><<<dim3(16, 4, 4), 256, HB_DSM>>>(
        (const uint32_t*)Bb, wh + o7, wl + o7, cb7, A);

    // ---- head (feats GEMM now on HMMA)
    build_F<<<1024, 256>>>(A, F, 1048576);
    hmma_feats<<<dim3(5, 16), 256, HB_DSM>>>(F, W1, b1, G);
    mlp2_softmax_tanh<<<2048, 32>>>(G, W2, b2, P1);

    build_neigh<<<640, 256>>>(P1, NG, 163840);
    gemm_neigh_add<<<dim3(10, 2, 16), 256>>>(NG, W1, G);
    mlp2_softmax_tanh<<<2048, 32>>>(G, W2, b2, out + 1280);

    final_mean_sq<<<5, 256>>>(out + 1280, out);
}

// round 16
// speedup vs baseline: 1.0596x; 1.0596x over previous
#include <cuda_runtime.h>
#include <cuda_bf16.h>
#include <cstdint>
#include <math.h>

#define BATCH 128
typedef unsigned long long ull;

// ---------------- f32x2 packed helpers (conv1 direct kernel) ---------------
__device__ __forceinline__ void fma2(ull& d, ull a, ull b) {
    asm("fma.rn.f32x2 %0, %1, %2, %0;" : "+l"(d) : "l"(a), "l"(b));
}
__device__ __forceinline__ ull bcast2(float x) {
    ull r; asm("mov.b64 %0, {%1, %1};" : "=l"(r) : "f"(x)); return r;
}
__device__ __forceinline__ ull pack2(float lo, float hi) {
    ull r; asm("mov.b64 %0, {%1, %2};" : "=l"(r) : "f"(lo), "f"(hi)); return r;
}
union F4U { float4 v; ull u[2]; };
union UF2 { ull u; float f[2]; };

// ---------------- HMMA helpers ----------------------------------------------
__device__ __forceinline__ uint32_t smem_u32(const void* p) {
    uint32_t a;
    asm("{ .reg .u64 t; cvta.to.shared.u64 t, %1; cvt.u32.u64 %0, t; }" : "=r"(a) : "l"(p));
    return a;
}
#define LDMX4(R, ADDR) \
    asm volatile("ldmatrix.sync.aligned.m8n8.x4.shared.b16 {%0,%1,%2,%3}, [%4];" \
        : "=r"((R)[0]), "=r"((R)[1]), "=r"((R)[2]), "=r"((R)[3]) : "r"(ADDR))

__device__ __forceinline__ void mma_bf16(float* d, const uint32_t* a, const uint32_t* b) {
    asm volatile(
        "mma.sync.aligned.m16n8k16.row.col.f32.bf16.bf16.f32 "
        "{%0,%1,%2,%3}, {%4,%5,%6,%7}, {%8,%9}, {%0,%1,%2,%3};"
        : "+f"(d[0]), "+f"(d[1]), "+f"(d[2]), "+f"(d[3])
        : "r"(a[0]), "r"(a[1]), "r"(a[2]), "r"(a[3]), "r"(b[0]), "r"(b[1]));
}

__device__ __forceinline__ uint32_t packbf2(float x, float y) {
    __nv_bfloat162 t = __floats2bfloat162_rn(x, y);
    return *(uint32_t*)&t;
}

// packed split: u32 = (hi bf16) | (lo bf16 << 16), where v ~= hi + lo
__device__ __forceinline__ uint32_t packsplit(float v) {
    __nv_bfloat16 h = __float2bfloat16(v);
    float lo = v - __bfloat162float(h);
    __nv_bfloat16 l = __float2bfloat16(lo);
    unsigned short hu = *(unsigned short*)&h, lu = *(unsigned short*)&l;
    return (uint32_t)hu | ((uint32_t)lu << 16);
}

// fast tanh via hardware EX2: tanh(x) = 1 - 2/(e^{2x}+1)
__device__ __forceinline__ float fast_tanh(float x) {
    float e = __expf(2.f * x);
    return 1.f - __fdividef(2.f, e + 1.f);
}

// ---------------- scratch --------------------------------------------------
__device__ float g_A[33554432];
__device__ float g_B[8388608];
__device__ float g_X[16 * 128 * 592];
__device__ float g_H[16 * 128 * 600];
__device__ float g_P1[16 * 128 * 10];
// stats: [0..256) = BN1 (sum at c, sq at 64+c); [256..2304) = BN2, 8 replicas
// of 256 (sum at c, sq at 128+c within each replica)
__device__ double g_stat[2304];
__device__ __nv_bfloat16 g_wh[6856704];
__device__ __nv_bfloat16 g_wl[6856704];

__device__ const int c_nidx[16][8] = {
    {1, 4, 5, -1, -1, -1, -1, -1},
    {0, 2, 5, 4, 6, -1, -1, -1},
    {1, 3, 6, 5, 7, -1, -1, -1},
    {2, 7, 6, -1, -1, -1, -1, -1},
    {0, 5, 8, 1, 9, -1, -1, -1},
    {1, 4, 6, 9, 0, 2, 8, 10},
    {2, 5, 7, 10, 1, 3, 9, 11},
    {3, 6, 11, 2, 10, -1, -1, -1},
    {4, 9, 12, 5, 13, -1, -1, -1},
    {5, 8, 10, 13, 4, 6, 12, 14},
    {6, 9, 11, 14, 5, 7, 13, 15},
    {7, 10, 15, 6, 14, -1, -1, -1},
    {8, 13, 9, -1, -1, -1, -1, -1},
    {9, 12, 14, 8, 10, -1, -1, -1},
    {10, 13, 15, 9, 11, -1, -1, -1},
    {11, 14, 10, -1, -1, -1, -1, -1},
};

// ---------------- one-shot split of ALL conv weights + stat zeroing ---------
__global__ void split_all(const float* __restrict__ w2, const float* __restrict__ w3,
                          const float* __restrict__ w4, const float* __restrict__ w5,
                          const float* __restrict__ w6, const float* __restrict__ w7,
                          __nv_bfloat16* __restrict__ wh, __nv_bfloat16* __restrict__ wl,
                          double* __restrict__ stat)
{
    int i = blockIdx.x * 256 + threadIdx.x;
    if (i < 2304) stat[i] = 0.0;
    if (i >= 6856704) return;
    const float* src; int off;
    if      (i <   73728) { src = w2; off = 0; }
    else if (i <  368640) { src = w3; off = 73728; }
    else if (i <  958464) { src = w4; off = 368640; }
    else if (i < 2138112) { src = w5; off = 958464; }
    else if (i < 4497408) { src = w6; off = 2138112; }
    else                  { src = w7; off = 4497408; }
    float v = src[i - off];
    __nv_bfloat16 h = __float2bfloat16(v);
    wh[i] = h;
    wl[i] = __float2bfloat16(v - __bfloat162float(h));
}

// ============================================================================
// HMMA bf16x3 implicit-GEMM conv with pre-split inputs.
// STATS=true (conv2): epilogue also accumulates per-cout sum/sumsq into
// 8-replica double stat array (replica = blockIdx.x & 7).
// ============================================================================
static constexpr int HB_DSM = 65536 + 1024;

template<int Cin, int Cout, int H, int W, bool RELU, bool PACKOUT, int KSPLIT = 1, bool STATS = false>
__global__ __launch_bounds__(256, 2)
void conv_hmma(const uint32_t* __restrict__ in,
               const __nv_bfloat16* __restrict__ wh, const __nv_bfloat16* __restrict__ wl,
               const float* __restrict__ bias, float* __restrict__ out,
               double* __restrict__ stat)
{
    constexpr int K  = Cin * 9;
    constexpr int HW = H * W;
    constexpr int NC  = K / 32;
    constexpr int NCZ = NC / KSPLIT;

    extern __shared__ char dsm_raw[];
    __shared__ float ssum[128], ssq[128];
    const uint32_t sb = (smem_u32(dsm_raw) + 1023u) & ~1023u;

    const int tid  = threadIdx.x;
    const int wid  = tid >> 5;
    const int lane = tid & 31;
    const int wm   = wid & 1;
    const int wn   = wid >> 1;
    const int n0   = blockIdx.x * 128;
    const int m0   = blockIdx.y * 128;
    const int kc0  = (KSPLIT > 1) ? blockIdx.z * NCZ : 0;
    if (KSPLIT > 1) out += (size_t)blockIdx.z * Cout * (BATCH * HW);

    const int lr = tid >> 1;
    const int lh = tid & 1;
    const int gn = n0 + lr;
    const int bidx = gn / HW;
    const int p    = gn & (HW - 1);
    const int y0   = p / W;
    const int x0   = p & (W - 1);
    const uint32_t* srcb = in + bidx * Cin * HW;
    const __nv_bfloat16* whp0 = wh + (m0 + lr) * K + lh * 16;
    const __nv_bfloat16* wlp0 = wl + (m0 + lr) * K + lh * 16;

    if (STATS && tid < 128) { ssum[tid] = 0.f; ssq[tid] = 0.f; }

    float acc[4][4][4];
    #pragma unroll
    for (int mt = 0; mt < 4; mt++)
        #pragma unroll
        for (int nt = 0; nt < 4; nt++)
            #pragma unroll
            for (int e = 0; e < 4; e++) acc[mt][nt][e] = 0.f;

    auto swz = [](int row, int ch) { return row * 64 + ((ch ^ ((row >> 1) & 3)) << 4); };
    const int c0 = 2 * lh;

    auto load_tiles = [&](int s, int kc) {
        const uint32_t tb = sb + s * 32768;
        {
            const uint4* ph = (const uint4*)(whp0 + kc * 32);
            const uint4* pl = (const uint4*)(wlp0 + kc * 32);
            uint4 h0 = __ldg(ph), h1 = __ldg(ph + 1);
            uint4 l0 = __ldg(pl), l1 = __ldg(pl + 1);
            asm volatile("st.shared.v4.b32 [%0], {%1,%2,%3,%4};" ::
                "r"(tb + swz(lr, c0)), "r"(h0.x), "r"(h0.y), "r"(h0.z), "r"(h0.w));
            asm volatile("st.shared.v4.b32 [%0], {%1,%2,%3,%4};" ::
                "r"(tb + swz(lr, c0 + 1)), "r"(h1.x), "r"(h1.y), "r"(h1.z), "r"(h1.w));
            asm volatile("st.shared.v4.b32 [%0], {%1,%2,%3,%4};" ::
                "r"(tb + 8192 + swz(lr, c0)), "r"(l0.x), "r"(l0.y), "r"(l0.z), "r"(l0.w));
            asm volatile("st.shared.v4.b32 [%0], {%1,%2,%3,%4};" ::
                "r"(tb + 8192 + swz(lr, c0 + 1)), "r"(l1.x), "r"(l1.y), "r"(l1.z), "r"(l1.w));
        }
        {
            int k = kc * 32 + lh * 16;
            int ci = k / 9;
            int f  = k - 9 * ci;
            int cioff = ci * HW;
            uint32_t w[16];
            #pragma unroll
            for (int j = 0; j < 16; j++) {
                int dy = (f * 11) >> 5;
                int dx = f - 3 * dy;
                int y = y0 + dy - 1, x = x0 + dx - 1;
                w[j] = ((unsigned)y < (unsigned)H && (unsigned)x < (unsigned)W)
                         ? __ldg(srcb + cioff + y * W + x) : 0u;
                f++; if (f == 9) { f = 0; cioff += HW; }
            }
            uint32_t Hw[8], Lw[8];
            #pragma unroll
            for (int j = 0; j < 8; j++) {
                Hw[j] = __byte_perm(w[2 * j], w[2 * j + 1], 0x5410);
                Lw[j] = __byte_perm(w[2 * j], w[2 * j + 1], 0x7632);
            }
            const uint32_t bb = tb + 16384;
            asm volatile("st.shared.v4.b32 [%0], {%1,%2,%3,%4};" ::
                "r"(bb + swz(lr, c0)), "r"(Hw[0]), "r"(Hw[1]), "r"(Hw[2]), "r"(Hw[3]));
            asm volatile("st.shared.v4.b32 [%0], {%1,%2,%3,%4};" ::
                "r"(bb + swz(lr, c0 + 1)), "r"(Hw[4]), "r"(Hw[5]), "r"(Hw[6]), "r"(Hw[7]));
            asm volatile("st.shared.v4.b32 [%0], {%1,%2,%3,%4};" ::
                "r"(bb + 8192 + swz(lr, c0)), "r"(Lw[0]), "r"(Lw[1]), "r"(Lw[2]), "r"(Lw[3]));
            asm volatile("st.shared.v4.b32 [%0], {%1,%2,%3,%4};" ::
                "r"(bb + 8192 + swz(lr, c0 + 1)), "r"(Lw[4]), "r"(Lw[5]), "r"(Lw[6]), "r"(Lw[7]));
        }
    };

    load_tiles(0, kc0);
    __syncthreads();

    for (int j = 0; j < NCZ; j++) {
        const int s = j & 1;
        if (j + 1 < NCZ) load_tiles(s ^ 1, kc0 + j + 1);

        const uint32_t aB = sb + s * 32768;
        const uint32_t bB = aB + 16384;

        #pragma unroll
        for (int ks = 0; ks < 2; ks++) {
            uint32_t bh[4][2], bl[4][2];
            #pragma unroll
            for (int ntp = 0; ntp < 2; ntp++) {
                int row = wn * 32 + ntp * 16 + ((lane >> 4) & 1) * 8 + (lane & 7);
                int ch  = ks * 2 + ((lane >> 3) & 1);
                uint32_t off = swz(row, ch);
                uint32_t t4[4];
                LDMX4(t4, bB + off);
                bh[ntp*2][0] = t4[0]; bh[ntp*2][1] = t4[1];
                bh[ntp*2+1][0] = t4[2]; bh[ntp*2+1][1] = t4[3];
                LDMX4(t4, bB + 8192 + off);
                bl[ntp*2][0] = t4[0]; bl[ntp*2][1] = t4[1];
                bl[ntp*2+1][0] = t4[2]; bl[ntp*2+1][1] = t4[3];
            }
            const int arow = wm * 64 + (lane & 7) + ((lane >> 3) & 1) * 8;
            const int ach  = ks * 2 + (lane >> 4);
            #pragma unroll
            for (int mt = 0; mt < 4; mt++) {
                uint32_t ah[4], al[4];
                int row = arow + mt * 16;
                uint32_t off = swz(row, ach);
                LDMX4(ah, aB + off);
                LDMX4(al, aB + 8192 + off);
                #pragma unroll
                for (int nt = 0; nt < 4; nt++) {
                    mma_bf16(acc[mt][nt], ah, bh[nt]);
                    mma_bf16(acc[mt][nt], ah, bl[nt]);
                    mma_bf16(acc[mt][nt], al, bh[nt]);
                }
            }
        }
        __syncthreads();
    }

    float rs[4][2], rq[4][2];
    if (STATS) {
        #pragma unroll
        for (int mt = 0; mt < 4; mt++)
            #pragma unroll
            for (int hh = 0; hh < 2; hh++) { rs[mt][hh] = 0.f; rq[mt][hh] = 0.f; }
    }

    #pragma unroll
    for (int mt = 0; mt < 4; mt++) {
        #pragma unroll
        for (int nt = 0; nt < 4; nt++) {
            int r0 = m0 + wm * 64 + mt * 16 + (lane >> 2);
            int cc = n0 + wn * 32 + nt * 8 + ((lane & 3) << 1);
            int b  = cc / HW;
            int pp = cc & (HW - 1);
            #pragma unroll
            for (int hh = 0; hh < 2; hh++) {
                int row = r0 + hh * 8;
                float bv = (KSPLIT == 1 || blockIdx.z == 0) ? bias[row] : 0.f;
                float2 v;
                v.x = acc[mt][nt][hh * 2 + 0] + bv;
                v.y = acc[mt][nt][hh * 2 + 1] + bv;
                if (RELU) { v.x = fmaxf(v.x, 0.f); v.y = fmaxf(v.y, 0.f); }
                if (STATS) {
                    rs[mt][hh] += v.x + v.y;
                    rq[mt][hh] += v.x * v.x + v.y * v.y;
                }
                if (PACKOUT) {
                    uint2 o;
                    o.x = packsplit(v.x);
                    o.y = packsplit(v.y);
                    *(uint2*)&((uint32_t*)out)[(b * Cout + row) * HW + pp] = o;
                } else {
                    *(float2*)&out[(b * Cout + row) * HW + pp] = v;
                }
            }
        }
    }

    if (STATS) {
        #pragma unroll
        for (int mt = 0; mt < 4; mt++) {
            #pragma unroll
            for (int hh = 0; hh < 2; hh++) {
                float s = rs[mt][hh], q = rq[mt][hh];
                s += __shfl_xor_sync(0xffffffffu, s, 1);
                q += __shfl_xor_sync(0xffffffffu, q, 1);
                s += __shfl_xor_sync(0xffffffffu, s, 2);
                q += __shfl_xor_sync(0xffffffffu, q, 2);
                if ((lane & 3) == 0) {
                    int row = wm * 64 + mt * 16 + (lane >> 2) + hh * 8;
                    atomicAdd(&ssum[row], s);
                    atomicAdd(&ssq[row], q);
                }
            }
        }
        __syncthreads();
        if (tid < 128) {
            double* rep = stat + (blockIdx.x & 7) * 256;
            atomicAdd(&rep[tid],       (double)ssum[tid]);
            atomicAdd(&rep[128 + tid], (double)ssq[tid]);
        }
    }
}

// ============================================================================
// HMMA bf16x3 head GEMM (unchanged winner).
// ============================================================================
__global__ __launch_bounds__(256, 2)
void hmma_feats(const float* __restrict__ F, const float* __restrict__ W1,
                const float* __restrict__ b1, float* __restrict__ G)
{
    constexpr int K = 512, NC = 16, N = 600;
    extern __shared__ char dsm_raw[];
    const uint32_t sb = (smem_u32(dsm_raw) + 1023u) & ~1023u;

    const int tid  = threadIdx.x;
    const int wid  = tid >> 5;
    const int lane = tid & 31;
    const int wm   = wid & 1;
    const int wn   = wid >> 1;
    const int n0   = blockIdx.x * 128;
    const int node = blockIdx.y;

    const int lr = tid >> 1;
    const int lh = tid & 1;
    const float* Fb = F + node * 128 * K + lr * K + lh * 16;
    const float* Wb = W1 + node * 592 * N + 80 * N;
    const float* bb1 = b1 + node * N;
    const int gn = n0 + lr;
    const bool nok = (gn < N);

    float acc[4][4][4];
    #pragma unroll
    for (int mt = 0; mt < 4; mt++)
        #pragma unroll
        for (int nt = 0; nt < 4; nt++)
            #pragma unroll
            for (int e = 0; e < 4; e++) acc[mt][nt][e] = 0.f;

    auto swz = [](int row, int ch) { return row * 64 + ((ch ^ ((row >> 1) & 3)) << 4); };
    const int c0 = 2 * lh;

    auto load_tiles = [&](int s, int kc) {
        const uint32_t tb = sb + s * 32768;
        {
            const float* fp = Fb + kc * 32;
            float4 w0 = *(const float4*)(fp + 0);
            float4 w1 = *(const float4*)(fp + 4);
            float4 w2 = *(const float4*)(fp + 8);
            float4 w3 = *(const float4*)(fp + 12);
            float v[16] = {w0.x,w0.y,w0.z,w0.w, w1.x,w1.y,w1.z,w1.w,
                           w2.x,w2.y,w2.z,w2.w, w3.x,w3.y,w3.z,w3.w};
            float hi[16], lo[16];
            #pragma unroll
            for (int j = 0; j < 16; j++) {
                __nv_bfloat16 h = __float2bfloat16(v[j]);
                hi[j] = __bfloat162float(h);
                lo[j] = v[j] - hi[j];
            }
            uint4 H0 = { packbf2(hi[0],hi[1]), packbf2(hi[2],hi[3]),
                         packbf2(hi[4],hi[5]), packbf2(hi[6],hi[7]) };
            uint4 H1 = { packbf2(hi[8],hi[9]), packbf2(hi[10],hi[11]),
                         packbf2(hi[12],hi[13]), packbf2(hi[14],hi[15]) };
            uint4 L0 = { packbf2(lo[0],lo[1]), packbf2(lo[2],lo[3]),
                         packbf2(lo[4],lo[5]), packbf2(lo[6],lo[7]) };
            uint4 L1 = { packbf2(lo[8],lo[9]), packbf2(lo[10],lo[11]),
                         packbf2(lo[12],lo[13]), packbf2(lo[14],lo[15]) };
            asm volatile("st.shared.v4.b32 [%0], {%1,%2,%3,%4};" ::
                "r"(tb + swz(lr, c0)), "r"(H0.x), "r"(H0.y), "r"(H0.z), "r"(H0.w));
            asm volatile("st.shared.v4.b32 [%0], {%1,%2,%3,%4};" ::
                "r"(tb + swz(lr, c0 + 1)), "r"(H1.x), "r"(H1.y), "r"(H1.z), "r"(H1.w));
            asm volatile("st.shared.v4.b32 [%0], {%1,%2,%3,%4};" ::
                "r"(tb + 8192 + swz(lr, c0)), "r"(L0.x), "r"(L0.y), "r"(L0.z), "r"(L0.w));
            asm volatile("st.shared.v4.b32 [%0], {%1,%2,%3,%4};" ::
                "r"(tb + 8192 + swz(lr, c0 + 1)), "r"(L1.x), "r"(L1.y), "r"(L1.z), "r"(L1.w));
        }
        {
            int k = kc * 32 + lh * 16;
            float v[16];
            #pragma unroll
            for (int j = 0; j < 16; j++)
                v[j] = nok ? __ldg(Wb + (k + j) * N + gn) : 0.f;
            float hi[16], lo[16];
            #pragma unroll
            for (int j = 0; j < 16; j++) {
                __nv_bfloat16 h = __float2bfloat16(v[j]);
                hi[j] = __bfloat162float(h);
                lo[j] = v[j] - hi[j];
            }
            uint4 H0 = { packbf2(hi[0],hi[1]), packbf2(hi[2],hi[3]),
                         packbf2(hi[4],hi[5]), packbf2(hi[6],hi[7]) };
            uint4 H1 = { packbf2(hi[8],hi[9]), packbf2(hi[10],hi[11]),
                         packbf2(hi[12],hi[13]), packbf2(hi[14],hi[15]) };
            uint4 L0 = { packbf2(lo[0],lo[1]), packbf2(lo[2],lo[3]),
                         packbf2(lo[4],lo[5]), packbf2(lo[6],lo[7]) };
            uint4 L1 = { packbf2(lo[8],lo[9]), packbf2(lo[10],lo[11]),
                         packbf2(lo[12],lo[13]), packbf2(lo[14],lo[15]) };
            const uint32_t bbuf = tb + 16384;
            asm volatile("st.shared.v4.b32 [%0], {%1,%2,%3,%4};" ::
                "r"(bbuf + swz(lr, c0)), "r"(H0.x), "r"(H0.y), "r"(H0.z), "r"(H0.w));
            asm volatile("st.shared.v4.b32 [%0], {%1,%2,%3,%4};" ::
                "r"(bbuf + swz(lr, c0 + 1)), "r"(H1.x), "r"(H1.y), "r"(H1.z), "r"(H1.w));
            asm volatile("st.shared.v4.b32 [%0], {%1,%2,%3,%4};" ::
                "r"(bbuf + 8192 + swz(lr, c0)), "r"(L0.x), "r"(L0.y), "r"(L0.z), "r"(L0.w));
            asm volatile("st.shared.v4.b32 [%0], {%1,%2,%3,%4};" ::
                "r"(bbuf + 8192 + swz(lr, c0 + 1)), "r"(L1.x), "r"(L1.y), "r"(L1.z), "r"(L1.w));
        }
    };

    load_tiles(0, 0);
    __syncthreads();

    for (int j = 0; j < NC; j++) {
        const int s = j & 1;
        if (j + 1 < NC) load_tiles(s ^ 1, j + 1);

        const uint32_t aB = sb + s * 32768;
        const uint32_t bB = aB + 16384;

        #pragma unroll
        for (int ks = 0; ks < 2; ks++) {
            uint32_t bh[4][2], bl[4][2];
            #pragma unroll
            for (int ntp = 0; ntp < 2; ntp++) {
                int row = wn * 32 + ntp * 16 + ((lane >> 4) & 1) * 8 + (lane & 7);
                int ch  = ks * 2 + ((lane >> 3) & 1);
                uint32_t off = swz(row, ch);
                uint32_t t4[4];
                LDMX4(t4, bB + off);
                bh[ntp*2][0] = t4[0]; bh[ntp*2][1] = t4[1];
                bh[ntp*2+1][0] = t4[2]; bh[ntp*2+1][1] = t4[3];
                LDMX4(t4, bB + 8192 + off);
                bl[ntp*2][0] = t4[0]; bl[ntp*2][1] = t4[1];
                bl[ntp*2+1][0] = t4[2]; bl[ntp*2+1][1] = t4[3];
            }
            const int arow = wm * 64 + (lane & 7) + ((lane >> 3) & 1) * 8;
            const int ach  = ks * 2 + (lane >> 4);
            #pragma unroll
            for (int mt = 0; mt < 4; mt++) {
                uint32_t ah[4], al[4];
                int row = arow + mt * 16;
                uint32_t off = swz(row, ach);
                LDMX4(ah, aB + off);
                LDMX4(al, aB + 8192 + off);
                #pragma unroll
                for (int nt = 0; nt < 4; nt++) {
                    mma_bf16(acc[mt][nt], ah, bh[nt]);
                    mma_bf16(acc[mt][nt], ah, bl[nt]);
                    mma_bf16(acc[mt][nt], al, bh[nt]);
                }
            }
        }
        __syncthreads();
    }

    float* Gb = G + node * 128 * N;
    #pragma unroll
    for (int mt = 0; mt < 4; mt++) {
        #pragma unroll
        for (int nt = 0; nt < 4; nt++) {
            int r0 = wm * 64 + mt * 16 + (lane >> 2);
            int cc = n0 + wn * 32 + nt * 8 + ((lane & 3) << 1);
            if (cc >= N) continue;
            float2 bv = *(const float2*)&bb1[cc];
            #pragma unroll
            for (int hh = 0; hh < 2; hh++) {
                int row = r0 + hh * 8;
                float2 v;
                v.x = acc[mt][nt][hh * 2 + 0] + bv.x;
                v.y = acc[mt][nt][hh * 2 + 1] + bv.y;
                *(float2*)&Gb[row * N + cc] = v;
            }
        }
    }
}

// ============================================================================
// conv1 (3->64) direct conv + FUSED BN-stat accumulation (unchanged winner).
// ============================================================================
__global__ __launch_bounds__(256) void conv1_direct_stats(
    const float* __restrict__ in, const float* __restrict__ wgt,
    const float* __restrict__ bias, float* __restrict__ out,
    double* __restrict__ stat)
{
    __shared__ __align__(16) float wT[27][64];
    __shared__ float inr[3][3][66];
    __shared__ float sval[64][65];

    const int tid = threadIdx.x;
    const int b   = blockIdx.x >> 6;
    const int y   = blockIdx.x & 63;
    const int x   = tid & 63;
    const int cog = tid >> 6;

    for (int i = tid; i < 1728; i += 256) {
        int co = i / 27, k = i - co * 27;
        wT[k][co] = wgt[i];
    }
    for (int i = tid; i < 594; i += 256) {
        int ci = i / 198, rem = i - ci * 198;
        int dy = rem / 66, xx = rem - dy * 66;
        int yy = y - 1 + dy, gx = xx - 1;
        float v = 0.f;
        if ((unsigned)yy < 64u && (unsigned)gx < 64u)
            v = in[(b * 3 + ci) * 4096 + yy * 64 + gx];
        inr[ci][dy][xx] = v;
    }
    __syncthreads();

    float iv[27];
    #pragma unroll
    for (int ci = 0; ci < 3; ci++)
        #pragma unroll
        for (int dy = 0; dy < 3; dy++)
            #pragma unroll
            for (int dx = 0; dx < 3; dx++)
                iv[ci * 9 + dy * 3 + dx] = inr[ci][dy][x + dx];

    ull acc2[8];
    #pragma unroll
    for (int p = 0; p < 8; p++) {
        float2 bb = *(const float2*)&bias[cog * 16 + p * 2];
        acc2[p] = pack2(bb.x, bb.y);
    }
    #pragma unroll
    for (int k = 0; k < 27; k++) {
        ull v2 = bcast2(iv[k]);
        F4U w0, w1, w2, w3;
        w0.v = *(const float4*)&wT[k][cog * 16 + 0];
        w1.v = *(const float4*)&wT[k][cog * 16 + 4];
        w2.v = *(const float4*)&wT[k][cog * 16 + 8];
        w3.v = *(const float4*)&wT[k][cog * 16 + 12];
        fma2(acc2[0], w0.u[0], v2); fma2(acc2[1], w0.u[1], v2);
        fma2(acc2[2], w1.u[0], v2); fma2(acc2[3], w1.u[1], v2);
        fma2(acc2[4], w2.u[0], v2); fma2(acc2[5], w2.u[1], v2);
        fma2(acc2[6], w3.u[0], v2); fma2(acc2[7], w3.u[1], v2);
    }

    #pragma unroll
    for (int p = 0; p < 8; p++) {
        UF2 u; u.u = acc2[p];
        #pragma unroll
        for (int h = 0; h < 2; h++) {
            int co = cog * 16 + p * 2 + h;
            float val = u.f[h];
            out[(b * 64 + co) * 4096 + y * 64 + x] = val;
            sval[co][x] = val;
        }
    }
    __syncthreads();

    if (tid < 64) {
        float s = 0.f, q = 0.f;
        #pragma unroll 8
        for (int px = 0; px < 64; px++) {
            float v = sval[tid][px];
            s += v;
            q += v * v;
        }
        atomicAdd(&stat[tid],      (double)s);
        atomicAdd(&stat[64 + tid], (double)q);
    }
}

// ---------------- fused finalize + BN + ReLU + MaxPool(3,2,1) ---------------
// stat: base pointer; per channel c: sum at [r*256+c], sq at [r*256+qoff+c],
// summed over R replicas. Scale/shift table built in smem per block.
__global__ void bn_relu_pool2(const float* __restrict__ in, uint32_t* __restrict__ out,
                              const float* __restrict__ g, const float* __restrict__ bta,
                              const double* __restrict__ stat, int qoff, int R, double inv,
                              int totalp, int H, int owsh, int cmask)
{
    __shared__ float sscale[128], sshift[128];
    if ((int)threadIdx.x <= cmask) {
        int c = threadIdx.x;
        double s = 0.0, q = 0.0;
        for (int r = 0; r < R; r++) {
            s += stat[r * 256 + c];
            q += stat[r * 256 + qoff + c];
        }
        double m = s * inv;
        float mean = (float)m;
        float var  = (float)(q * inv - m * m);
        float sc = g[c] * rsqrtf(var + 1e-5f);
        sscale[c] = sc;
        sshift[c] = bta[c] - mean * sc;
    }
    __syncthreads();

    int OW = H >> 1;
    for (int i = blockIdx.x * blockDim.x + threadIdx.x; i < totalp;
         i += gridDim.x * blockDim.x) {
        int oxp = i & ((1 << (owsh - 1)) - 1);
        int t   = i >> (owsh - 1);
        int oy  = t & (OW - 1);
        int bc  = t >> owsh;
        int c   = bc & cmask;
        float scale = sscale[c];
        float shift = sshift[c];
        const float* src = in + (long long)bc * H * H;
        int xb = 4 * oxp - 1;
        float m0 = 0.f, m1 = 0.f;
        #pragma unroll
        for (int dy = 0; dy < 3; dy++) {
            int y = 2 * oy - 1 + dy;
            if ((unsigned)y >= (unsigned)H) continue;
            const float* row = src + y * H;
            float v[5];
            #pragma unroll
            for (int j = 0; j < 5; j++) {
                int x = xb + j;
                v[j] = ((unsigned)x < (unsigned)H) ? fmaf(row[x], scale, shift) : 0.f;
            }
            m0 = fmaxf(m0, fmaxf(fmaxf(v[0], v[1]), v[2]));
            m1 = fmaxf(m1, fmaxf(fmaxf(v[2], v[3]), v[4]));
        }
        uint2 o;
        o.x = packsplit(m0);
        o.y = packsplit(m1);
        *(uint2*)&out[(bc * OW + oy) * OW + 2 * oxp] = o;
    }
}

// ---------------- MaxPool2d(3,2,1), packed-split output ---------------------
__global__ void maxpool3s2(const float* __restrict__ in, uint32_t* __restrict__ out,
                           int total, int H, int W, int owsh)
{
    int OW = W >> 1;
    for (int i = blockIdx.x * blockDim.x + threadIdx.x; i < total;
         i += gridDim.x * blockDim.x) {
        int ox = i & (OW - 1);
        int t  = i >> owsh;
        int oy = t & (OW - 1);
        int bc = t >> owsh;
        const float* src = in + (long long)bc * H * W;
        float m = -INFINITY;
        #pragma unroll
        for (int dy = 0; dy < 3; dy++) {
            int y = 2 * oy - 1 + dy;
            if ((unsigned)y >= (unsigned)H) continue;
            #pragma unroll
            for (int dx = 0; dx < 3; dx++) {
                int x = 2 * ox - 1 + dx;
                if ((unsigned)x >= (unsigned)W) continue;
                m = fmaxf(m, src[y * W + x]);
            }
        }
        out[i] = packsplit(m);
    }
}

// ---------------- head: G += neigh @ W1[0:80] (K=80, scalar) ----------------
__global__ __launch_bounds__(256) void gemm_neigh_add(
    const float* __restrict__ A, const float* __restrict__ Bw,
    float* __restrict__ C)
{
    const int M = 128, N = 600, KA = 80;
    const int node = blockIdx.z;
    A  += node * M * KA;
    Bw += node * 592 * N;
    C  += node * M * N;

    __shared__ __align__(16) float As[16][68];
    __shared__ __align__(16) float Bs[16][68];

    const int tid = threadIdx.x;
    const int m0 = blockIdx.y * 64;
    const int n0 = blockIdx.x * 64;
    const int tm = tid >> 4;
    const int tn = tid & 15;

    float acc[4][4] = {};

    for (int k0 = 0; k0 < KA; k0 += 16) {
        #pragma unroll
        for (int i = 0; i < 4; i++) {
            int lin = tid + i * 256;
            int kk = lin & 15;
            int mm = lin >> 4;
            As[kk][mm] = A[(m0 + mm) * KA + k0 + kk];
        }
        #pragma unroll
        for (int i = 0; i < 4; i++) {
            int lin = tid + i * 256;
            int nn = lin & 63;
            int kk = lin >> 6;
            int gn = n0 + nn;
            Bs[kk][nn] = (gn < N) ? Bw[(k0 + kk) * N + gn] : 0.f;
        }
        __syncthreads();
        #pragma unroll
        for (int kk = 0; kk < 16; kk++) {
            float4 a4 = *(const float4*)&As[kk][tm * 4];
            float4 b4 = *(const float4*)&Bs[kk][tn * 4];
            float av[4] = {a4.x, a4.y, a4.z, a4.w};
            float bv[4] = {b4.x, b4.y, b4.z, b4.w};
            #pragma unroll
            for (int i = 0; i < 4; i++)
                #pragma unroll
                for (int j = 0; j < 4; j++)
                    acc[i][j] = fmaf(av[i], bv[j], acc[i][j]);
        }
        __syncthreads();
    }

    #pragma unroll
    for (int i = 0; i < 4; i++) {
        int m = m0 + tm * 4 + i;
        #pragma unroll
        for (int j = 0; j < 4; j++) {
            int gn = n0 + tn * 4 + j;
            if (gn < N)
                C[m * N + gn] += acc[i][j];
        }
    }
}

// ---------------- MLP stage 2 + softmax (fast tanh fused on load) -----------
__global__ void mlp2_softmax_tanh(const float* __restrict__ h, const float* __restrict__ W2,
                                  const float* __restrict__ b2, float* __restrict__ out)
{
    int nb = blockIdx.x;
    int node = nb >> 7;
    int b    = nb & 127;
    int lane = threadIdx.x;

    const float* hrow = h  + (node * 128 + b) * 600;
    const float* w    = W2 + node * 600 * 10;

    float acc[10];
    #pragma unroll
    for (int o = 0; o < 10; o++) acc[o] = 0.f;

    for (int i = lane; i < 600; i += 32) {
        float hv = fast_tanh(hrow[i]);
        const float* wr = w + i * 10;
        #pragma unroll
        for (int o = 0; o < 10; o++)
            acc[o] = fmaf(hv, wr[o], acc[o]);
    }
    #pragma unroll
    for (int o = 0; o < 10; o++)
        #pragma unroll
        for (int s = 16; s > 0; s >>= 1)
            acc[o] += __shfl_down_sync(0xffffffffu, acc[o], s);

    if (lane == 0) {
        float lg[10];
        float mx = -INFINITY;
        #pragma unroll
        for (int o = 0; o < 10; o++) {
            lg[o] = acc[o] + b2[node * 10 + o];
            mx = fmaxf(mx, lg[o]);
        }
        float se = 0.f;
        #pragma unroll
        for (int o = 0; o < 10; o++) { lg[o] = __expf(lg[o] - mx); se += lg[o]; }
        float inv = __fdividef(1.f, se);
        #pragma unroll
        for (int o = 0; o < 10; o++)
            out[(node * 128 + b) * 10 + o] = lg[o] * inv;
    }
}

// ---------------- head glue ---------------------------------------------------
__global__ void build_F(const float* __restrict__ p, float* __restrict__ F, int total)
{
    for (int i = blockIdx.x * blockDim.x + threadIdx.x; i < total;
         i += gridDim.x * blockDim.x) {
        int cf = i & 511;
        int t  = i >> 9;
        int b  = t & 127;
        int n  = t >> 7;
        int idx = ((b * 512 + cf) << 4) + n;
        float v = p[idx] + p[idx + 1048576] + p[idx + 2097152] + p[idx + 3145728];
        F[i] = fmaxf(v, 0.f);
    }
}

__global__ void build_neigh(const float* __restrict__ P1, float* __restrict__ NG, int total)
{
    for (int i = blockIdx.x * blockDim.x + threadIdx.x; i < total;
         i += gridDim.x * blockDim.x) {
        int j = i % 80;
        int t = i / 80;
        int b = t & 127;
        int n = t >> 7;
        int s   = j / 10;
        int cls = j - s * 10;
        int nb  = c_nidx[n][s];
        float v = (nb >= 0) ? P1[(nb * 128 + b) * 10 + cls] : 0.f;
        NG[(n * 128 + b) * 80 + j] = v;
    }
}

__global__ void final_mean_sq(const float* __restrict__ preds2, float* __restrict__ out)
{
    int t = blockIdx.x * blockDim.x + threadIdx.x;
    if (t >= 1280) return;
    int b = t / 10, c = t - (t / 10) * 10;
    float s = 0.f;
    #pragma unroll
    for (int n = 0; n < 16; n++)
        s += preds2[(n * 128 + b) * 10 + c];
    s *= (1.f / 16.f);
    out[t] = s * s;
}

// ---------------- launcher -----------------------------------------------------
extern "C" void kernel_launch(void* const* d_in, const int* in_sizes, int n_in,
                              void* d_out, int out_size)
{
    const float* x     = (const float*)d_in[0];
    const float* cw1   = (const float*)d_in[1];
    const float* cb1   = (const float*)d_in[2];
    const float* bn1g  = (const float*)d_in[3];
    const float* bn1b  = (const float*)d_in[4];
    const float* cw2   = (const float*)d_in[5];
    const float* cb2   = (const float*)d_in[6];
    const float* bn2g  = (const float*)d_in[7];
    const float* bn2b  = (const float*)d_in[8];
    const float* cw3   = (const float*)d_in[9];
    const float* cb3   = (const float*)d_in[10];
    const float* cw4   = (const float*)d_in[11];
    const float* cb4   = (const float*)d_in[12];
    const float* cw5   = (const float*)d_in[13];
    const float* cb5   = (const float*)d_in[14];
    const float* cw6   = (const float*)d_in[15];
    const float* cb6   = (const float*)d_in[16];
    const float* cw7   = (const float*)d_in[17];
    const float* cb7   = (const float*)d_in[18];
    const float* W1    = (const float*)d_in[19];
    const float* b1    = (const float*)d_in[20];
    const float* W2    = (const float*)d_in[21];
    const float* b2    = (const float*)d_in[22];
    float* out = (float*)d_out;

    float *A, *Bb, *X, *G, *P1;
    double* stat;
    __nv_bfloat16 *wh, *wl;
    cudaGetSymbolAddress((void**)&A,    g_A);
    cudaGetSymbolAddress((void**)&Bb,   g_B);
    cudaGetSymbolAddress((void**)&X,    g_X);
    cudaGetSymbolAddress((void**)&G,    g_H);
    cudaGetSymbolAddress((void**)&P1,   g_P1);
    cudaGetSymbolAddress((void**)&stat, g_stat);
    cudaGetSymbolAddress((void**)&wh,   g_wh);
    cudaGetSymbolAddress((void**)&wl,   g_wl);

    float* F  = X;
    float* NG = X + 1048576;

    const int o2 = 0, o3 = 73728, o4 = 368640, o5 = 958464, o6 = 2138112, o7 = 4497408;

    cudaFuncSetAttribute(conv_hmma<64, 128, 32, 32, false, false, 1, true>, cudaFuncAttributeMaxDynamicSharedMemorySize, HB_DSM);
    cudaFuncSetAttribute(conv_hmma<128, 256, 16, 16, true, true>,    cudaFuncAttributeMaxDynamicSharedMemorySize, HB_DSM);
    cudaFuncSetAttribute(conv_hmma<256, 256, 16, 16, true, false>,   cudaFuncAttributeMaxDynamicSharedMemorySize, HB_DSM);
    cudaFuncSetAttribute(conv_hmma<256, 512, 8, 8, true, true>,      cudaFuncAttributeMaxDynamicSharedMemorySize, HB_DSM);
    cudaFuncSetAttribute(conv_hmma<512, 512, 8, 8, true, false>,     cudaFuncAttributeMaxDynamicSharedMemorySize, HB_DSM);
    cudaFuncSetAttribute(conv_hmma<512, 512, 4, 4, false, false, 4>, cudaFuncAttributeMaxDynamicSharedMemorySize, HB_DSM);
    cudaFuncSetAttribute(hmma_feats, cudaFuncAttributeMaxDynamicSharedMemorySize, HB_DSM);

    // ---- split weights + zero all stat replicas (one launch, precedes conv1)
    split_all<<<26785, 256>>>(cw2, cw3, cw4, cw5, cw6, cw7, wh, wl, stat);

    // ---- conv1 (3->64, 64x64) + fused BN1 stats; pool+finalize fused next
    conv1_direct_stats<<<8192, 256>>>(x, cw1, cb1, A, stat);
    bn_relu_pool2<<<16384, 256>>>(A, (uint32_t*)Bb, bn1g, bn1b,
                                  stat, 64, 1, 1.0 / 524288.0, 4194304, 64, 5, 63);

    // ---- conv2 (64->128, 32x32): packed in -> fp32 out, BN2 stats fused
    conv_hmma<64, 128, 32, 32, false, false, 1, true><<<dim3(1024, 1), 256, HB_DSM>>>(
        (const uint32_t*)Bb, wh + o2, wl + o2, cb2, A, stat + 256);
    bn_relu_pool2<<<8192, 256>>>(A, (uint32_t*)Bb, bn2g, bn2b,
                                 stat + 256, 128, 8, 1.0 / 131072.0, 2097152, 32, 4, 127);

    // ---- conv3 (packed -> packed), conv4 (packed -> fp32), pool -> packed
    conv_hmma<128, 256, 16, 16, true, true><<<dim3(256, 2), 256, HB_DSM>>>(
        (const uint32_t*)Bb, wh + o3, wl + o3, cb3, A, stat);
    conv_hmma<256, 256, 16, 16, true, false><<<dim3(256, 2), 256, HB_DSM>>>(
        (const uint32_t*)A, wh + o4, wl + o4, cb4, Bb, stat);
    maxpool3s2<<<4096, 256>>>(Bb, (uint32_t*)A, 2097152, 16, 16, 3);

    // ---- conv5 (packed -> packed), conv6 (packed -> fp32), pool -> packed
    conv_hmma<256, 512, 8, 8, true, true><<<dim3(64, 4), 256, HB_DSM>>>(
        (const uint32_t*)A, wh + o5, wl + o5, cb5, Bb, stat);
    conv_hmma<512, 512, 8, 8, true, false><<<dim3(64, 4), 256, HB_DSM>>>(
        (const uint32_t*)Bb, wh + o6, wl + o6, cb6, A, stat);
    maxpool3s2<<<2048, 256>>>(A, (uint32_t*)Bb, 1048576, 8, 8, 2);

    // ---- conv7 split-K=4 (packed in -> fp32 partials)
    conv_hmma<512, 512, 4, 4, false, false, 4><<<dim3(16, 4, 4), 256, HB_DSM>>>(
        (const uint32_t*)Bb, wh + o7, wl + o7, cb7, A, stat);

    // ---- head (feats GEMM on HMMA)
    build_F<<<1024, 256>>>(A, F, 1048576);
    hmma_feats<<<dim3(5, 16), 256, HB_DSM>>>(F, W1, b1, G);
    mlp2_softmax_tanh<<<2048, 32>>>(G, W2, b2, P1);

    build_neigh<<<640, 256>>>(P1, NG, 163840);
    gemm_neigh_add<<<dim3(10, 2, 16), 256>>>(NG, W1, G);
    mlp2_softmax_tanh<<<2048, 32>>>(G, W2, b2, out + 1280);

    final_mean_sq<<<5, 256>>>(out + 1280, out);
}

// round 17
// speedup vs baseline: 1.0877x; 1.0265x over previous
#include <cuda_runtime.h>
#include <cuda_bf16.h>
#include <cstdint>
#include <math.h>

#define BATCH 128
typedef unsigned long long ull;

// ---------------- f32x2 packed helpers (conv1 direct kernel) ---------------
__device__ __forceinline__ void fma2(ull& d, ull a, ull b) {
    asm("fma.rn.f32x2 %0, %1, %2, %0;" : "+l"(d) : "l"(a), "l"(b));
}
__device__ __forceinline__ ull bcast2(float x) {
    ull r; asm("mov.b64 %0, {%1, %1};" : "=l"(r) : "f"(x)); return r;
}
__device__ __forceinline__ ull pack2(float lo, float hi) {
    ull r; asm("mov.b64 %0, {%1, %2};" : "=l"(r) : "f"(lo), "f"(hi)); return r;
}
union F4U { float4 v; ull u[2]; };
union UF2 { ull u; float f[2]; };

// ---------------- HMMA helpers ----------------------------------------------
__device__ __forceinline__ uint32_t smem_u32(const void* p) {
    uint32_t a;
    asm("{ .reg .u64 t; cvta.to.shared.u64 t, %1; cvt.u32.u64 %0, t; }" : "=r"(a) : "l"(p));
    return a;
}
#define LDMX4(R, ADDR) \
    asm volatile("ldmatrix.sync.aligned.m8n8.x4.shared.b16 {%0,%1,%2,%3}, [%4];" \
        : "=r"((R)[0]), "=r"((R)[1]), "=r"((R)[2]), "=r"((R)[3]) : "r"(ADDR))
#define CPASYNC16(SM, GP) \
    asm volatile("cp.async.cg.shared.global [%0], [%1], 16;" :: "r"(SM), "l"(GP))
#define CP_COMMIT() asm volatile("cp.async.commit_group;" ::: "memory")
#define CP_WAIT0()  asm volatile("cp.async.wait_group 0;" ::: "memory")

__device__ __forceinline__ void mma_bf16(float* d, const uint32_t* a, const uint32_t* b) {
    asm volatile(
        "mma.sync.aligned.m16n8k16.row.col.f32.bf16.bf16.f32 "
        "{%0,%1,%2,%3}, {%4,%5,%6,%7}, {%8,%9}, {%0,%1,%2,%3};"
        : "+f"(d[0]), "+f"(d[1]), "+f"(d[2]), "+f"(d[3])
        : "r"(a[0]), "r"(a[1]), "r"(a[2]), "r"(a[3]), "r"(b[0]), "r"(b[1]));
}

__device__ __forceinline__ uint32_t packbf2(float x, float y) {
    __nv_bfloat162 t = __floats2bfloat162_rn(x, y);
    return *(uint32_t*)&t;
}

// packed split: u32 = (hi bf16) | (lo bf16 << 16), where v ~= hi + lo
__device__ __forceinline__ uint32_t packsplit(float v) {
    __nv_bfloat16 h = __float2bfloat16(v);
    float lo = v - __bfloat162float(h);
    __nv_bfloat16 l = __float2bfloat16(lo);
    unsigned short hu = *(unsigned short*)&h, lu = *(unsigned short*)&l;
    return (uint32_t)hu | ((uint32_t)lu << 16);
}

// fast tanh via hardware EX2: tanh(x) = 1 - 2/(e^{2x}+1)
__device__ __forceinline__ float fast_tanh(float x) {
    float e = __expf(2.f * x);
    return 1.f - __fdividef(2.f, e + 1.f);
}

// ---------------- scratch --------------------------------------------------
__device__ float g_A[33554432];
__device__ float g_B[8388608];
__device__ float g_X[16 * 128 * 592];
__device__ float g_H[16 * 128 * 600];
__device__ float g_P1[16 * 128 * 10];
__device__ double g_stat[2304];
__device__ __nv_bfloat16 g_wh[6856704];
__device__ __nv_bfloat16 g_wl[6856704];

__device__ const int c_nidx[16][8] = {
    {1, 4, 5, -1, -1, -1, -1, -1},
    {0, 2, 5, 4, 6, -1, -1, -1},
    {1, 3, 6, 5, 7, -1, -1, -1},
    {2, 7, 6, -1, -1, -1, -1, -1},
    {0, 5, 8, 1, 9, -1, -1, -1},
    {1, 4, 6, 9, 0, 2, 8, 10},
    {2, 5, 7, 10, 1, 3, 9, 11},
    {3, 6, 11, 2, 10, -1, -1, -1},
    {4, 9, 12, 5, 13, -1, -1, -1},
    {5, 8, 10, 13, 4, 6, 12, 14},
    {6, 9, 11, 14, 5, 7, 13, 15},
    {7, 10, 15, 6, 14, -1, -1, -1},
    {8, 13, 9, -1, -1, -1, -1, -1},
    {9, 12, 14, 8, 10, -1, -1, -1},
    {10, 13, 15, 9, 11, -1, -1, -1},
    {11, 14, 10, -1, -1, -1, -1, -1},
};

// ---------------- one-shot split of ALL conv weights + stat zeroing ---------
__global__ void split_all(const float* __restrict__ w2, const float* __restrict__ w3,
                          const float* __restrict__ w4, const float* __restrict__ w5,
                          const float* __restrict__ w6, const float* __restrict__ w7,
                          __nv_bfloat16* __restrict__ wh, __nv_bfloat16* __restrict__ wl,
                          double* __restrict__ stat)
{
    int i = blockIdx.x * 256 + threadIdx.x;
    if (i < 2304) stat[i] = 0.0;
    if (i >= 6856704) return;
    const float* src; int off;
    if      (i <   73728) { src = w2; off = 0; }
    else if (i <  368640) { src = w3; off = 73728; }
    else if (i <  958464) { src = w4; off = 368640; }
    else if (i < 2138112) { src = w5; off = 958464; }
    else if (i < 4497408) { src = w6; off = 2138112; }
    else                  { src = w7; off = 4497408; }
    float v = src[i - off];
    __nv_bfloat16 h = __float2bfloat16(v);
    wh[i] = h;
    wl[i] = __float2bfloat16(v - __bfloat162float(h));
}

// ============================================================================
// HMMA bf16x3 implicit-GEMM conv, latency-decoupled loader:
// A via cp.async (no reg staging), B LDGs issued BEFORE the MMA section and
// consumed (perm+STS) after it. STATS=true: fused BN stats (8 replicas).
// ============================================================================
static constexpr int HB_DSM = 65536 + 1024;

template<int Cin, int Cout, int H, int W, bool RELU, bool PACKOUT, int KSPLIT = 1, bool STATS = false>
__global__ __launch_bounds__(256, 2)
void conv_hmma(const uint32_t* __restrict__ in,
               const __nv_bfloat16* __restrict__ wh, const __nv_bfloat16* __restrict__ wl,
               const float* __restrict__ bias, float* __restrict__ out,
               double* __restrict__ stat)
{
    constexpr int K  = Cin * 9;
    constexpr int HW = H * W;
    constexpr int NC  = K / 32;
    constexpr int NCZ = NC / KSPLIT;

    extern __shared__ char dsm_raw[];
    __shared__ float ssum[128], ssq[128];
    const uint32_t sb = (smem_u32(dsm_raw) + 1023u) & ~1023u;

    const int tid  = threadIdx.x;
    const int wid  = tid >> 5;
    const int lane = tid & 31;
    const int wm   = wid & 1;
    const int wn   = wid >> 1;
    const int n0   = blockIdx.x * 128;
    const int m0   = blockIdx.y * 128;
    const int kc0  = (KSPLIT > 1) ? blockIdx.z * NCZ : 0;
    if (KSPLIT > 1) out += (size_t)blockIdx.z * Cout * (BATCH * HW);

    const int lr = tid >> 1;
    const int lh = tid & 1;
    const int gn = n0 + lr;
    const int bidx = gn / HW;
    const int p    = gn & (HW - 1);
    const int y0   = p / W;
    const int x0   = p & (W - 1);
    const uint32_t* srcb = in + bidx * Cin * HW;
    const __nv_bfloat16* whp0 = wh + (m0 + lr) * K + lh * 16;
    const __nv_bfloat16* wlp0 = wl + (m0 + lr) * K + lh * 16;

    if (STATS && tid < 128) { ssum[tid] = 0.f; ssq[tid] = 0.f; }

    float acc[4][4][4];
    #pragma unroll
    for (int mt = 0; mt < 4; mt++)
        #pragma unroll
        for (int nt = 0; nt < 4; nt++)
            #pragma unroll
            for (int e = 0; e < 4; e++) acc[mt][nt][e] = 0.f;

    auto swz = [](int row, int ch) { return row * 64 + ((ch ^ ((row >> 1) & 3)) << 4); };
    const int c0 = 2 * lh;

    // A-side: fire-and-forget cp.async of pre-split weights
    auto issue_A = [&](int s, int kc) {
        const uint32_t tb = sb + s * 32768;
        const char* ph = (const char*)(whp0 + kc * 32);
        const char* pl = (const char*)(wlp0 + kc * 32);
        CPASYNC16(tb + swz(lr, c0),            ph);
        CPASYNC16(tb + swz(lr, c0 + 1),        ph + 16);
        CPASYNC16(tb + 8192 + swz(lr, c0),     pl);
        CPASYNC16(tb + 8192 + swz(lr, c0 + 1), pl + 16);
    };
    // B-side: issue gather LDGs into regs (consumed later)
    auto issue_B = [&](int kc, uint32_t* w) {
        int k = kc * 32 + lh * 16;
        int ci = k / 9;
        int f  = k - 9 * ci;
        int cioff = ci * HW;
        #pragma unroll
        for (int j = 0; j < 16; j++) {
            int dy = (f * 11) >> 5;
            int dx = f - 3 * dy;
            int y = y0 + dy - 1, x = x0 + dx - 1;
            w[j] = ((unsigned)y < (unsigned)H && (unsigned)x < (unsigned)W)
                     ? __ldg(srcb + cioff + y * W + x) : 0u;
            f++; if (f == 9) { f = 0; cioff += HW; }
        }
    };
    auto store_B = [&](int s, const uint32_t* w) {
        uint32_t Hw[8], Lw[8];
        #pragma unroll
        for (int j = 0; j < 8; j++) {
            Hw[j] = __byte_perm(w[2 * j], w[2 * j + 1], 0x5410);
            Lw[j] = __byte_perm(w[2 * j], w[2 * j + 1], 0x7632);
        }
        const uint32_t bb = sb + s * 32768 + 16384;
        asm volatile("st.shared.v4.b32 [%0], {%1,%2,%3,%4};" ::
            "r"(bb + swz(lr, c0)), "r"(Hw[0]), "r"(Hw[1]), "r"(Hw[2]), "r"(Hw[3]));
        asm volatile("st.shared.v4.b32 [%0], {%1,%2,%3,%4};" ::
            "r"(bb + swz(lr, c0 + 1)), "r"(Hw[4]), "r"(Hw[5]), "r"(Hw[6]), "r"(Hw[7]));
        asm volatile("st.shared.v4.b32 [%0], {%1,%2,%3,%4};" ::
            "r"(bb + 8192 + swz(lr, c0)), "r"(Lw[0]), "r"(Lw[1]), "r"(Lw[2]), "r"(Lw[3]));
        asm volatile("st.shared.v4.b32 [%0], {%1,%2,%3,%4};" ::
            "r"(bb + 8192 + swz(lr, c0 + 1)), "r"(Lw[4]), "r"(Lw[5]), "r"(Lw[6]), "r"(Lw[7]));
    };

    // ---- prologue: chunk kc0 into buffer 0
    issue_A(0, kc0);
    CP_COMMIT();
    {
        uint32_t w0[16];
        issue_B(kc0, w0);
        store_B(0, w0);
    }
    CP_WAIT0();
    __syncthreads();

    uint32_t wst[16];
    for (int j = 0; j < NCZ; j++) {
        const int s = j & 1;
        const bool more = (j + 1 < NCZ);
        if (more) {
            issue_A(s ^ 1, kc0 + j + 1);
            CP_COMMIT();
            issue_B(kc0 + j + 1, wst);      // LDGs in flight during MMA section
        }

        const uint32_t aB = sb + s * 32768;
        const uint32_t bB = aB + 16384;

        #pragma unroll
        for (int ks = 0; ks < 2; ks++) {
            uint32_t bh[4][2], bl[4][2];
            #pragma unroll
            for (int ntp = 0; ntp < 2; ntp++) {
                int row = wn * 32 + ntp * 16 + ((lane >> 4) & 1) * 8 + (lane & 7);
                int ch  = ks * 2 + ((lane >> 3) & 1);
                uint32_t off = swz(row, ch);
                uint32_t t4[4];
                LDMX4(t4, bB + off);
                bh[ntp*2][0] = t4[0]; bh[ntp*2][1] = t4[1];
                bh[ntp*2+1][0] = t4[2]; bh[ntp*2+1][1] = t4[3];
                LDMX4(t4, bB + 8192 + off);
                bl[ntp*2][0] = t4[0]; bl[ntp*2][1] = t4[1];
                bl[ntp*2+1][0] = t4[2]; bl[ntp*2+1][1] = t4[3];
            }
            const int arow = wm * 64 + (lane & 7) + ((lane >> 3) & 1) * 8;
            const int ach  = ks * 2 + (lane >> 4);
            #pragma unroll
            for (int mt = 0; mt < 4; mt++) {
                uint32_t ah[4], al[4];
                int row = arow + mt * 16;
                uint32_t off = swz(row, ach);
                LDMX4(ah, aB + off);
                LDMX4(al, aB + 8192 + off);
                #pragma unroll
                for (int nt = 0; nt < 4; nt++) {
                    mma_bf16(acc[mt][nt], ah, bh[nt]);
                    mma_bf16(acc[mt][nt], ah, bl[nt]);
                    mma_bf16(acc[mt][nt], al, bh[nt]);
                }
            }
        }

        if (more) {
            store_B(s ^ 1, wst);            // LDG latency hidden by MMAs above
            CP_WAIT0();
        }
        __syncthreads();
    }

    float rs[4][2], rq[4][2];
    if (STATS) {
        #pragma unroll
        for (int mt = 0; mt < 4; mt++)
            #pragma unroll
            for (int hh = 0; hh < 2; hh++) { rs[mt][hh] = 0.f; rq[mt][hh] = 0.f; }
    }

    #pragma unroll
    for (int mt = 0; mt < 4; mt++) {
        #pragma unroll
        for (int nt = 0; nt < 4; nt++) {
            int r0 = m0 + wm * 64 + mt * 16 + (lane >> 2);
            int cc = n0 + wn * 32 + nt * 8 + ((lane & 3) << 1);
            int b  = cc / HW;
            int pp = cc & (HW - 1);
            #pragma unroll
            for (int hh = 0; hh < 2; hh++) {
                int row = r0 + hh * 8;
                float bv = (KSPLIT == 1 || blockIdx.z == 0) ? bias[row] : 0.f;
                float2 v;
                v.x = acc[mt][nt][hh * 2 + 0] + bv;
                v.y = acc[mt][nt][hh * 2 + 1] + bv;
                if (RELU) { v.x = fmaxf(v.x, 0.f); v.y = fmaxf(v.y, 0.f); }
                if (STATS) {
                    rs[mt][hh] += v.x + v.y;
                    rq[mt][hh] += v.x * v.x + v.y * v.y;
                }
                if (PACKOUT) {
                    uint2 o;
                    o.x = packsplit(v.x);
                    o.y = packsplit(v.y);
                    *(uint2*)&((uint32_t*)out)[(b * Cout + row) * HW + pp] = o;
                } else {
                    *(float2*)&out[(b * Cout + row) * HW + pp] = v;
                }
            }
        }
    }

    if (STATS) {
        #pragma unroll
        for (int mt = 0; mt < 4; mt++) {
            #pragma unroll
            for (int hh = 0; hh < 2; hh++) {
                float s = rs[mt][hh], q = rq[mt][hh];
                s += __shfl_xor_sync(0xffffffffu, s, 1);
                q += __shfl_xor_sync(0xffffffffu, q, 1);
                s += __shfl_xor_sync(0xffffffffu, s, 2);
                q += __shfl_xor_sync(0xffffffffu, q, 2);
                if ((lane & 3) == 0) {
                    int row = wm * 64 + mt * 16 + (lane >> 2) + hh * 8;
                    atomicAdd(&ssum[row], s);
                    atomicAdd(&ssq[row], q);
                }
            }
        }
        __syncthreads();
        if (tid < 128) {
            double* rep = stat + (blockIdx.x & 7) * 256;
            atomicAdd(&rep[tid],       (double)ssum[tid]);
            atomicAdd(&rep[128 + tid], (double)ssq[tid]);
        }
    }
}

// ============================================================================
// HMMA bf16x3 head GEMM (unchanged winner).
// ============================================================================
__global__ __launch_bounds__(256, 2)
void hmma_feats(const float* __restrict__ F, const float* __restrict__ W1,
                const float* __restrict__ b1, float* __restrict__ G)
{
    constexpr int K = 512, NC = 16, N = 600;
    extern __shared__ char dsm_raw[];
    const uint32_t sb = (smem_u32(dsm_raw) + 1023u) & ~1023u;

    const int tid  = threadIdx.x;
    const int wid  = tid >> 5;
    const int lane = tid & 31;
    const int wm   = wid & 1;
    const int wn   = wid >> 1;
    const int n0   = blockIdx.x * 128;
    const int node = blockIdx.y;

    const int lr = tid >> 1;
    const int lh = tid & 1;
    const float* Fb = F + node * 128 * K + lr * K + lh * 16;
    const float* Wb = W1 + node * 592 * N + 80 * N;
    const float* bb1 = b1 + node * N;
    const int gn = n0 + lr;
    const bool nok = (gn < N);

    float acc[4][4][4];
    #pragma unroll
    for (int mt = 0; mt < 4; mt++)
        #pragma unroll
        for (int nt = 0; nt < 4; nt++)
            #pragma unroll
            for (int e = 0; e < 4; e++) acc[mt][nt][e] = 0.f;

    auto swz = [](int row, int ch) { return row * 64 + ((ch ^ ((row >> 1) & 3)) << 4); };
    const int c0 = 2 * lh;

    auto load_tiles = [&](int s, int kc) {
        const uint32_t tb = sb + s * 32768;
        {
            const float* fp = Fb + kc * 32;
            float4 w0 = *(const float4*)(fp + 0);
            float4 w1 = *(const float4*)(fp + 4);
            float4 w2 = *(const float4*)(fp + 8);
            float4 w3 = *(const float4*)(fp + 12);
            float v[16] = {w0.x,w0.y,w0.z,w0.w, w1.x,w1.y,w1.z,w1.w,
                           w2.x,w2.y,w2.z,w2.w, w3.x,w3.y,w3.z,w3.w};
            float hi[16], lo[16];
            #pragma unroll
            for (int j = 0; j < 16; j++) {
                __nv_bfloat16 h = __float2bfloat16(v[j]);
                hi[j] = __bfloat162float(h);
                lo[j] = v[j] - hi[j];
            }
            uint4 H0 = { packbf2(hi[0],hi[1]), packbf2(hi[2],hi[3]),
                         packbf2(hi[4],hi[5]), packbf2(hi[6],hi[7]) };
            uint4 H1 = { packbf2(hi[8],hi[9]), packbf2(hi[10],hi[11]),
                         packbf2(hi[12],hi[13]), packbf2(hi[14],hi[15]) };
            uint4 L0 = { packbf2(lo[0],lo[1]), packbf2(lo[2],lo[3]),
                         packbf2(lo[4],lo[5]), packbf2(lo[6],lo[7]) };
            uint4 L1 = { packbf2(lo[8],lo[9]), packbf2(lo[10],lo[11]),
                         packbf2(lo[12],lo[13]), packbf2(lo[14],lo[15]) };
            asm volatile("st.shared.v4.b32 [%0], {%1,%2,%3,%4};" ::
                "r"(tb + swz(lr, c0)), "r"(H0.x), "r"(H0.y), "r"(H0.z), "r"(H0.w));
            asm volatile("st.shared.v4.b32 [%0], {%1,%2,%3,%4};" ::
                "r"(tb + swz(lr, c0 + 1)), "r"(H1.x), "r"(H1.y), "r"(H1.z), "r"(H1.w));
            asm volatile("st.shared.v4.b32 [%0], {%1,%2,%3,%4};" ::
                "r"(tb + 8192 + swz(lr, c0)), "r"(L0.x), "r"(L0.y), "r"(L0.z), "r"(L0.w));
            asm volatile("st.shared.v4.b32 [%0], {%1,%2,%3,%4};" ::
                "r"(tb + 8192 + swz(lr, c0 + 1)), "r"(L1.x), "r"(L1.y), "r"(L1.z), "r"(L1.w));
        }
        {
            int k = kc * 32 + lh * 16;
            float v[16];
            #pragma unroll
            for (int j = 0; j < 16; j++)
                v[j] = nok ? __ldg(Wb + (k + j) * N + gn) : 0.f;
            float hi[16], lo[16];
            #pragma unroll
            for (int j = 0; j < 16; j++) {
                __nv_bfloat16 h = __float2bfloat16(v[j]);
                hi[j] = __bfloat162float(h);
                lo[j] = v[j] - hi[j];
            }
            uint4 H0 = { packbf2(hi[0],hi[1]), packbf2(hi[2],hi[3]),
                         packbf2(hi[4],hi[5]), packbf2(hi[6],hi[7]) };
            uint4 H1 = { packbf2(hi[8],hi[9]), packbf2(hi[10],hi[11]),
                         packbf2(hi[12],hi[13]), packbf2(hi[14],hi[15]) };
            uint4 L0 = { packbf2(lo[0],lo[1]), packbf2(lo[2],lo[3]),
                         packbf2(lo[4],lo[5]), packbf2(lo[6],lo[7]) };
            uint4 L1 = { packbf2(lo[8],lo[9]), packbf2(lo[10],lo[11]),
                         packbf2(lo[12],lo[13]), packbf2(lo[14],lo[15]) };
            const uint32_t bbuf = tb + 16384;
            asm volatile("st.shared.v4.b32 [%0], {%1,%2,%3,%4};" ::
                "r"(bbuf + swz(lr, c0)), "r"(H0.x), "r"(H0.y), "r"(H0.z), "r"(H0.w));
            asm volatile("st.shared.v4.b32 [%0], {%1,%2,%3,%4};" ::
                "r"(bbuf + swz(lr, c0 + 1)), "r"(H1.x), "r"(H1.y), "r"(H1.z), "r"(H1.w));
            asm volatile("st.shared.v4.b32 [%0], {%1,%2,%3,%4};" ::
                "r"(bbuf + 8192 + swz(lr, c0)), "r"(L0.x), "r"(L0.y), "r"(L0.z), "r"(L0.w));
            asm volatile("st.shared.v4.b32 [%0], {%1,%2,%3,%4};" ::
                "r"(bbuf + 8192 + swz(lr, c0 + 1)), "r"(L1.x), "r"(L1.y), "r"(L1.z), "r"(L1.w));
        }
    };

    load_tiles(0, 0);
    __syncthreads();

    for (int j = 0; j < NC; j++) {
        const int s = j & 1;
        if (j + 1 < NC) load_tiles(s ^ 1, j + 1);

        const uint32_t aB = sb + s * 32768;
        const uint32_t bB = aB + 16384;

        #pragma unroll
        for (int ks = 0; ks < 2; ks++) {
            uint32_t bh[4][2], bl[4][2];
            #pragma unroll
            for (int ntp = 0; ntp < 2; ntp++) {
                int row = wn * 32 + ntp * 16 + ((lane >> 4) & 1) * 8 + (lane & 7);
                int ch  = ks * 2 + ((lane >> 3) & 1);
                uint32_t off = swz(row, ch);
                uint32_t t4[4];
                LDMX4(t4, bB + off);
                bh[ntp*2][0] = t4[0]; bh[ntp*2][1] = t4[1];
                bh[ntp*2+1][0] = t4[2]; bh[ntp*2+1][1] = t4[3];
                LDMX4(t4, bB + 8192 + off);
                bl[ntp*2][0] = t4[0]; bl[ntp*2][1] = t4[1];
                bl[ntp*2+1][0] = t4[2]; bl[ntp*2+1][1] = t4[3];
            }
            const int arow = wm * 64 + (lane & 7) + ((lane >> 3) & 1) * 8;
            const int ach  = ks * 2 + (lane >> 4);
            #pragma unroll
            for (int mt = 0; mt < 4; mt++) {
                uint32_t ah[4], al[4];
                int row = arow + mt * 16;
                uint32_t off = swz(row, ach);
                LDMX4(ah, aB + off);
                LDMX4(al, aB + 8192 + off);
                #pragma unroll
                for (int nt = 0; nt < 4; nt++) {
                    mma_bf16(acc[mt][nt], ah, bh[nt]);
                    mma_bf16(acc[mt][nt], ah, bl[nt]);
                    mma_bf16(acc[mt][nt], al, bh[nt]);
                }
            }
        }
        __syncthreads();
    }

    float* Gb = G + node * 128 * N;
    #pragma unroll
    for (int mt = 0; mt < 4; mt++) {
        #pragma unroll
        for (int nt = 0; nt < 4; nt++) {
            int r0 = wm * 64 + mt * 16 + (lane >> 2);
            int cc = n0 + wn * 32 + nt * 8 + ((lane & 3) << 1);
            if (cc >= N) continue;
            float2 bv = *(const float2*)&bb1[cc];
            #pragma unroll
            for (int hh = 0; hh < 2; hh++) {
                int row = r0 + hh * 8;
                float2 v;
                v.x = acc[mt][nt][hh * 2 + 0] + bv.x;
                v.y = acc[mt][nt][hh * 2 + 1] + bv.y;
                *(float2*)&Gb[row * N + cc] = v;
            }
        }
    }
}

// ============================================================================
// conv1 (3->64) direct conv + FUSED BN-stat accumulation (unchanged winner).
// ============================================================================
__global__ __launch_bounds__(256) void conv1_direct_stats(
    const float* __restrict__ in, const float* __restrict__ wgt,
    const float* __restrict__ bias, float* __restrict__ out,
    double* __restrict__ stat)
{
    __shared__ __align__(16) float wT[27][64];
    __shared__ float inr[3][3][66];
    __shared__ float sval[64][65];

    const int tid = threadIdx.x;
    const int b   = blockIdx.x >> 6;
    const int y   = blockIdx.x & 63;
    const int x   = tid & 63;
    const int cog = tid >> 6;

    for (int i = tid; i < 1728; i += 256) {
        int co = i / 27, k = i - co * 27;
        wT[k][co] = wgt[i];
    }
    for (int i = tid; i < 594; i += 256) {
        int ci = i / 198, rem = i - ci * 198;
        int dy = rem / 66, xx = rem - dy * 66;
        int yy = y - 1 + dy, gx = xx - 1;
        float v = 0.f;
        if ((unsigned)yy < 64u && (unsigned)gx < 64u)
            v = in[(b * 3 + ci) * 4096 + yy * 64 + gx];
        inr[ci][dy][xx] = v;
    }
    __syncthreads();

    float iv[27];
    #pragma unroll
    for (int ci = 0; ci < 3; ci++)
        #pragma unroll
        for (int dy = 0; dy < 3; dy++)
            #pragma unroll
            for (int dx = 0; dx < 3; dx++)
                iv[ci * 9 + dy * 3 + dx] = inr[ci][dy][x + dx];

    ull acc2[8];
    #pragma unroll
    for (int p = 0; p < 8; p++) {
        float2 bb = *(const float2*)&bias[cog * 16 + p * 2];
        acc2[p] = pack2(bb.x, bb.y);
    }
    #pragma unroll
    for (int k = 0; k < 27; k++) {
        ull v2 = bcast2(iv[k]);
        F4U w0, w1, w2, w3;
        w0.v = *(const float4*)&wT[k][cog * 16 + 0];
        w1.v = *(const float4*)&wT[k][cog * 16 + 4];
        w2.v = *(const float4*)&wT[k][cog * 16 + 8];
        w3.v = *(const float4*)&wT[k][cog * 16 + 12];
        fma2(acc2[0], w0.u[0], v2); fma2(acc2[1], w0.u[1], v2);
        fma2(acc2[2], w1.u[0], v2); fma2(acc2[3], w1.u[1], v2);
        fma2(acc2[4], w2.u[0], v2); fma2(acc2[5], w2.u[1], v2);
        fma2(acc2[6], w3.u[0], v2); fma2(acc2[7], w3.u[1], v2);
    }

    #pragma unroll
    for (int p = 0; p < 8; p++) {
        UF2 u; u.u = acc2[p];
        #pragma unroll
        for (int h = 0; h < 2; h++) {
            int co = cog * 16 + p * 2 + h;
            float val = u.f[h];
            out[(b * 64 + co) * 4096 + y * 64 + x] = val;
            sval[co][x] = val;
        }
    }
    __syncthreads();

    if (tid < 64) {
        float s = 0.f, q = 0.f;
        #pragma unroll 8
        for (int px = 0; px < 64; px++) {
            float v = sval[tid][px];
            s += v;
            q += v * v;
        }
        atomicAdd(&stat[tid],      (double)s);
        atomicAdd(&stat[64 + tid], (double)q);
    }
}

// ---------------- fused finalize + BN + ReLU + MaxPool(3,2,1) ---------------
__global__ void bn_relu_pool2(const float* __restrict__ in, uint32_t* __restrict__ out,
                              const float* __restrict__ g, const float* __restrict__ bta,
                              const double* __restrict__ stat, int qoff, int R, double inv,
                              int totalp, int H, int owsh, int cmask)
{
    __shared__ float sscale[128], sshift[128];
    if ((int)threadIdx.x <= cmask) {
        int c = threadIdx.x;
        double s = 0.0, q = 0.0;
        for (int r = 0; r < R; r++) {
            s += stat[r * 256 + c];
            q += stat[r * 256 + qoff + c];
        }
        double m = s * inv;
        float mean = (float)m;
        float var  = (float)(q * inv - m * m);
        float sc = g[c] * rsqrtf(var + 1e-5f);
        sscale[c] = sc;
        sshift[c] = bta[c] - mean * sc;
    }
    __syncthreads();

    int OW = H >> 1;
    for (int i = blockIdx.x * blockDim.x + threadIdx.x; i < totalp;
         i += gridDim.x * blockDim.x) {
        int oxp = i & ((1 << (owsh - 1)) - 1);
        int t   = i >> (owsh - 1);
        int oy  = t & (OW - 1);
        int bc  = t >> owsh;
        int c   = bc & cmask;
        float scale = sscale[c];
        float shift = sshift[c];
        const float* src = in + (long long)bc * H * H;
        int xb = 4 * oxp - 1;
        float m0 = 0.f, m1 = 0.f;
        #pragma unroll
        for (int dy = 0; dy < 3; dy++) {
            int y = 2 * oy - 1 + dy;
            if ((unsigned)y >= (unsigned)H) continue;
            const float* row = src + y * H;
            float v[5];
            #pragma unroll
            for (int j = 0; j < 5; j++) {
                int x = xb + j;
                v[j] = ((unsigned)x < (unsigned)H) ? fmaf(row[x], scale, shift) : 0.f;
            }
            m0 = fmaxf(m0, fmaxf(fmaxf(v[0], v[1]), v[2]));
            m1 = fmaxf(m1, fmaxf(fmaxf(v[2], v[3]), v[4]));
        }
        uint2 o;
        o.x = packsplit(m0);
        o.y = packsplit(m1);
        *(uint2*)&out[(bc * OW + oy) * OW + 2 * oxp] = o;
    }
}

// ---------------- MaxPool2d(3,2,1), packed-split output ---------------------
__global__ void maxpool3s2(const float* __restrict__ in, uint32_t* __restrict__ out,
                           int total, int H, int W, int owsh)
{
    int OW = W >> 1;
    for (int i = blockIdx.x * blockDim.x + threadIdx.x; i < total;
         i += gridDim.x * blockDim.x) {
        int ox = i & (OW - 1);
        int t  = i >> owsh;
        int oy = t & (OW - 1);
        int bc = t >> owsh;
        const float* src = in + (long long)bc * H * W;
        float m = -INFINITY;
        #pragma unroll
        for (int dy = 0; dy < 3; dy++) {
            int y = 2 * oy - 1 + dy;
            if ((unsigned)y >= (unsigned)H) continue;
            #pragma unroll
            for (int dx = 0; dx < 3; dx++) {
                int x = 2 * ox - 1 + dx;
                if ((unsigned)x >= (unsigned)W) continue;
                m = fmaxf(m, src[y * W + x]);
            }
        }
        out[i] = packsplit(m);
    }
}

// ---------------- head: G += neigh @ W1[0:80] (K=80, scalar) ----------------
__global__ __launch_bounds__(256) void gemm_neigh_add(
    const float* __restrict__ A, const float* __restrict__ Bw,
    float* __restrict__ C)
{
    const int M = 128, N = 600, KA = 80;
    const int node = blockIdx.z;
    A  += node * M * KA;
    Bw += node * 592 * N;
    C  += node * M * N;

    __shared__ __align__(16) float As[16][68];
    __shared__ __align__(16) float Bs[16][68];

    const int tid = threadIdx.x;
    const int m0 = blockIdx.y * 64;
    const int n0 = blockIdx.x * 64;
    const int tm = tid >> 4;
    const int tn = tid & 15;

    float acc[4][4] = {};

    for (int k0 = 0; k0 < KA; k0 += 16) {
        #pragma unroll
        for (int i = 0; i < 4; i++) {
            int lin = tid + i * 256;
            int kk = lin & 15;
            int mm = lin >> 4;
            As[kk][mm] = A[(m0 + mm) * KA + k0 + kk];
        }
        #pragma unroll
        for (int i = 0; i < 4; i++) {
            int lin = tid + i * 256;
            int nn = lin & 63;
            int kk = lin >> 6;
            int gn = n0 + nn;
            Bs[kk][nn] = (gn < N) ? Bw[(k0 + kk) * N + gn] : 0.f;
        }
        __syncthreads();
        #pragma unroll
        for (int kk = 0; kk < 16; kk++) {
            float4 a4 = *(const float4*)&As[kk][tm * 4];
            float4 b4 = *(const float4*)&Bs[kk][tn * 4];
            float av[4] = {a4.x, a4.y, a4.z, a4.w};
            float bv[4] = {b4.x, b4.y, b4.z, b4.w};
            #pragma unroll
            for (int i = 0; i < 4; i++)
                #pragma unroll
                for (int j = 0; j < 4; j++)
                    acc[i][j] = fmaf(av[i], bv[j], acc[i][j]);
        }
        __syncthreads();
    }

    #pragma unroll
    for (int i = 0; i < 4; i++) {
        int m = m0 + tm * 4 + i;
        #pragma unroll
        for (int j = 0; j < 4; j++) {
            int gn = n0 + tn * 4 + j;
            if (gn < N)
                C[m * N + gn] += acc[i][j];
        }
    }
}

// ---------------- MLP stage 2 + softmax (fast tanh fused on load) -----------
__global__ void mlp2_softmax_tanh(const float* __restrict__ h, const float* __restrict__ W2,
                                  const float* __restrict__ b2, float* __restrict__ out)
{
    int nb = blockIdx.x;
    int node = nb >> 7;
    int b    = nb & 127;
    int lane = threadIdx.x;

    const float* hrow = h  + (node * 128 + b) * 600;
    const float* w    = W2 + node * 600 * 10;

    float acc[10];
    #pragma unroll
    for (int o = 0; o < 10; o++) acc[o] = 0.f;

    for (int i = lane; i < 600; i += 32) {
        float hv = fast_tanh(hrow[i]);
        const float* wr = w + i * 10;
        #pragma unroll
        for (int o = 0; o < 10; o++)
            acc[o] = fmaf(hv, wr[o], acc[o]);
    }
    #pragma unroll
    for (int o = 0; o < 10; o++)
        #pragma unroll
        for (int s = 16; s > 0; s >>= 1)
            acc[o] += __shfl_down_sync(0xffffffffu, acc[o], s);

    if (lane == 0) {
        float lg[10];
        float mx = -INFINITY;
        #pragma unroll
        for (int o = 0; o < 10; o++) {
            lg[o] = acc[o] + b2[node * 10 + o];
            mx = fmaxf(mx, lg[o]);
        }
        float se = 0.f;
        #pragma unroll
        for (int o = 0; o < 10; o++) { lg[o] = __expf(lg[o] - mx); se += lg[o]; }
        float inv = __fdividef(1.f, se);
        #pragma unroll
        for (int o = 0; o < 10; o++)
            out[(node * 128 + b) * 10 + o] = lg[o] * inv;
    }
}

// ---------------- head glue ---------------------------------------------------
__global__ void build_F(const float* __restrict__ p, float* __restrict__ F, int total)
{
    for (int i = blockIdx.x * blockDim.x + threadIdx.x; i < total;
         i += gridDim.x * blockDim.x) {
        int cf = i & 511;
        int t  = i >> 9;
        int b  = t & 127;
        int n  = t >> 7;
        int idx = ((b * 512 + cf) << 4) + n;
        float v = p[idx] + p[idx + 1048576] + p[idx + 2097152] + p[idx + 3145728];
        F[i] = fmaxf(v, 0.f);
    }
}

__global__ void build_neigh(const float* __restrict__ P1, float* __restrict__ NG, int total)
{
    for (int i = blockIdx.x * blockDim.x + threadIdx.x; i < total;
         i += gridDim.x * blockDim.x) {
        int j = i % 80;
        int t = i / 80;
        int b = t & 127;
        int n = t >> 7;
        int s   = j / 10;
        int cls = j - s * 10;
        int nb  = c_nidx[n][s];
        float v = (nb >= 0) ? P1[(nb * 128 + b) * 10 + cls] : 0.f;
        NG[(n * 128 + b) * 80 + j] = v;
    }
}

__global__ void final_mean_sq(const float* __restrict__ preds2, float* __restrict__ out)
{
    int t = blockIdx.x * blockDim.x + threadIdx.x;
    if (t >= 1280) return;
    int b = t / 10, c = t - (t / 10) * 10;
    float s = 0.f;
    #pragma unroll
    for (int n = 0; n < 16; n++)
        s += preds2[(n * 128 + b) * 10 + c];
    s *= (1.f / 16.f);
    out[t] = s * s;
}

// ---------------- launcher -----------------------------------------------------
extern "C" void kernel_launch(void* const* d_in, const int* in_sizes, int n_in,
                              void* d_out, int out_size)
{
    const float* x     = (const float*)d_in[0];
    const float* cw1   = (const float*)d_in[1];
    const float* cb1   = (const float*)d_in[2];
    const float* bn1g  = (const float*)d_in[3];
    const float* bn1b  = (const float*)d_in[4];
    const float* cw2   = (const float*)d_in[5];
    const float* cb2   = (const float*)d_in[6];
    const float* bn2g  = (const float*)d_in[7];
    const float* bn2b  = (const float*)d_in[8];
    const float* cw3   = (const float*)d_in[9];
    const float* cb3   = (const float*)d_in[10];
    const float* cw4   = (const float*)d_in[11];
    const float* cb4   = (const float*)d_in[12];
    const float* cw5   = (const float*)d_in[13];
    const float* cb5   = (const float*)d_in[14];
    const float* cw6   = (const float*)d_in[15];
    const float* cb6   = (const float*)d_in[16];
    const float* cw7   = (const float*)d_in[17];
    const float* cb7   = (const float*)d_in[18];
    const float* W1    = (const float*)d_in[19];
    const float* b1    = (const float*)d_in[20];
    const float* W2    = (const float*)d_in[21];
    const float* b2    = (const float*)d_in[22];
    float* out = (float*)d_out;

    float *A, *Bb, *X, *G, *P1;
    double* stat;
    __nv_bfloat16 *wh, *wl;
    cudaGetSymbolAddress((void**)&A,    g_A);
    cudaGetSymbolAddress((void**)&Bb,   g_B);
    cudaGetSymbolAddress((void**)&X,    g_X);
    cudaGetSymbolAddress((void**)&G,    g_H);
    cudaGetSymbolAddress((void**)&P1,   g_P1);
    cudaGetSymbolAddress((void**)&stat, g_stat);
    cudaGetSymbolAddress((void**)&wh,   g_wh);
    cudaGetSymbolAddress((void**)&wl,   g_wl);

    float* F  = X;
    float* NG = X + 1048576;

    const int o2 = 0, o3 = 73728, o4 = 368640, o5 = 958464, o6 = 2138112, o7 = 4497408;

    cudaFuncSetAttribute(conv_hmma<64, 128, 32, 32, false, false, 1, true>, cudaFuncAttributeMaxDynamicSharedMemorySize, HB_DSM);
    cudaFuncSetAttribute(conv_hmma<128, 256, 16, 16, true, true>,    cudaFuncAttributeMaxDynamicSharedMemorySize, HB_DSM);
    cudaFuncSetAttribute(conv_hmma<256, 256, 16, 16, true, false>,   cudaFuncAttributeMaxDynamicSharedMemorySize, HB_DSM);
    cudaFuncSetAttribute(conv_hmma<256, 512, 8, 8, true, true>,      cudaFuncAttributeMaxDynamicSharedMemorySize, HB_DSM);
    cudaFuncSetAttribute(conv_hmma<512, 512, 8, 8, true, false>,     cudaFuncAttributeMaxDynamicSharedMemorySize, HB_DSM);
    cudaFuncSetAttribute(conv_hmma<512, 512, 4, 4, false, false, 4>, cudaFuncAttributeMaxDynamicSharedMemorySize, HB_DSM);
    cudaFuncSetAttribute(hmma_feats, cudaFuncAttributeMaxDynamicSharedMemorySize, HB_DSM);

    // ---- split weights + zero all stat replicas (one launch, precedes conv1)
    split_all<<<26785, 256>>>(cw2, cw3, cw4, cw5, cw6, cw7, wh, wl, stat);

    // ---- conv1 (3->64, 64x64) + fused BN1 stats; pool+finalize fused next
    conv1_direct_stats<<<8192, 256>>>(x, cw1, cb1, A, stat);
    bn_relu_pool2<<<16384, 256>>>(A, (uint32_t*)Bb, bn1g, bn1b,
                                  stat, 64, 1, 1.0 / 524288.0, 4194304, 64, 5, 63);

    // ---- conv2 (64->128, 32x32): packed in -> fp32 out, BN2 stats fused
    conv_hmma<64, 128, 32, 32, false, false, 1, true><<<dim3(1024, 1), 256, HB_DSM>>>(
        (const uint32_t*)Bb, wh + o2, wl + o2, cb2, A, stat + 256);
    bn_relu_pool2<<<8192, 256>>>(A, (uint32_t*)Bb, bn2g, bn2b,
                                 stat + 256, 128, 8, 1.0 / 131072.0, 2097152, 32, 4, 127);

    // ---- conv3 (packed -> packed), conv4 (packed -> fp32), pool -> packed
    conv_hmma<128, 256, 16, 16, true, true><<<dim3(256, 2), 256, HB_DSM>>>(
        (const uint32_t*)Bb, wh + o3, wl + o3, cb3, A, stat);
    conv_hmma<256, 256, 16, 16, true, false><<<dim3(256, 2), 256, HB_DSM>>>(
        (const uint32_t*)A, wh + o4, wl + o4, cb4, Bb, stat);
    maxpool3s2<<<4096, 256>>>(Bb, (uint32_t*)A, 2097152, 16, 16, 3);

    // ---- conv5 (packed -> packed), conv6 (packed -> fp32), pool -> packed
    conv_hmma<256, 512, 8, 8, true, true><<<dim3(64, 4), 256, HB_DSM>>>(
        (const uint32_t*)A, wh + o5, wl + o5, cb5, Bb, stat);
    conv_hmma<512, 512, 8, 8, true, false><<<dim3(64, 4), 256, HB_DSM>>>(
        (const uint32_t*)Bb, wh + o6, wl + o6, cb6, A, stat);
    maxpool3s2<<<2048, 256>>>(A, (uint32_t*)Bb, 1048576, 8, 8, 2);

    // ---- conv7 split-K=4 (packed in -> fp32 partials)
    conv_hmma<512, 512, 4, 4, false, false, 4><<<dim3(16, 4, 4), 256, HB_DSM>>>(
        (const uint32_t*)Bb, wh + o7, wl + o7, cb7, A, stat);

    // ---- head (feats GEMM on HMMA)
    build_F<<<1024, 256>>>(A, F, 1048576);
    hmma_feats<<<dim3(5, 16), 256, HB_DSM>>>(F, W1, b1, G);
    mlp2_softmax_tanh<<<2048, 32>>>(G, W2, b2, P1);

    build_neigh<<<640, 256>>>(P1, NG, 163840);
    gemm_neigh_add<<<dim3(10, 2, 16), 256>>>(NG, W1, G);
    mlp2_softmax_tanh<<<2048, 32>>>(G, W2, b2, out + 1280);

    final_mean_sq<<<5, 256>>>(out + 1280, out);
}